// round 9
// baseline (speedup 1.0000x reference)
#include <cuda_runtime.h>
#include <cuda_fp16.h>
#include <math.h>
#include <stdint.h>

#define N_NODES   100000
#define N_EDGES   200000
#define EMB       300
#define EMB2      600
#define TW        640          // padded width of split intermediate t
#define NUM_LAYER 5
#define NUM_GRAPHS 5000
#define BN_EPS    1e-5f

// ---------------- device scratch (allocation-free) ----------------
__device__ __align__(16) float g_h[N_NODES * EMB];
__device__ __align__(16) float g_agg[N_NODES * EMB];
__device__ __align__(16) float g_tab[9 * EMB];
__device__ float g_stats[2 * EMB];     // [0:EMB) sum(y), [EMB:2EMB) sum(y^2)
__device__ float g_counts[NUM_GRAPHS];
// split intermediate t (fp16 hi/lo), cols [600,640) stay zero (never written)
__device__ __align__(16) __half g_th[(size_t)N_NODES * TW];
__device__ __align__(16) __half g_tl[(size_t)N_NODES * TW];
// transposed + split weights (fp16 hi/lo), zero-padded: max 384x640 = 245760
__device__ __align__(16) __half g_wth[245760];
__device__ __align__(16) __half g_wtl[245760];

__device__ __forceinline__ uint32_t smem_u32(const void* p) {
    uint32_t a;
    asm("{ .reg .u64 t; cvta.to.shared.u64 t, %1; cvt.u32.u64 %0, t; }" : "=r"(a) : "l"(p));
    return a;
}

// ---------------- h0 = x_emb1[x0] + x_emb2[x1] ----------------
__global__ void init_h_kernel(const int* __restrict__ x,
                              const float* __restrict__ e1,
                              const float* __restrict__ e2) {
    int idx = blockIdx.x * blockDim.x + threadIdx.x;
    if (idx >= N_NODES * EMB) return;
    int i = idx / EMB, c = idx - i * EMB;
    int a = x[2 * i], b = x[2 * i + 1];
    g_h[idx] = e1[a * EMB + c] + e2[b * EMB + c];
}

// ---------------- per-layer eemb table ----------------
__global__ void build_tab_kernel(const float* __restrict__ e1,
                                 const float* __restrict__ e2, int l) {
    int idx = blockIdx.x * blockDim.x + threadIdx.x;
    if (idx >= 9 * EMB) return;
    int t = idx / EMB, c = idx - t * EMB;
    int a = t / 3, b = t - a * 3;
    g_tab[idx] = e1[(l * 6 + a) * EMB + c] + e2[(l * 3 + b) * EMB + c];
}

__global__ void zero_stats_kernel() {
    int idx = blockIdx.x * blockDim.x + threadIdx.x;
    if (idx < 2 * EMB) g_stats[idx] = 0.f;
}

// ---------------- agg = h + tab[0]  (first layer only) ----------------
__global__ void init_agg_kernel() {
    int idx = blockIdx.x * blockDim.x + threadIdx.x;
    if (idx >= N_NODES * EMB) return;
    g_agg[idx] = g_h[idx] + g_tab[idx % EMB];
}

// ---------------- edge scatter: agg[dst] += h[src] + tab[attr] ----------------
__global__ __launch_bounds__(256) void scatter_edges_kernel(
        const int* __restrict__ ei, const int* __restrict__ ea) {
    int e = blockIdx.x * 8 + (threadIdx.x >> 5);
    if (e >= N_EDGES) return;
    int lane = threadIdx.x & 31;
    int src = ei[e];
    int dst = ei[N_EDGES + e];
    int t = ea[2 * e] * 3 + ea[2 * e + 1];
    const float4* hs = (const float4*)(g_h + (size_t)src * EMB);
    const float4* tb = (const float4*)(g_tab + t * EMB);
    float* ag = g_agg + (size_t)dst * EMB;
    #pragma unroll
    for (int i = lane; i < EMB / 4; i += 32) {
        float4 hv = hs[i];
        float4 tv = tb[i];
        atomicAdd(&ag[4 * i + 0], hv.x + tv.x);
        atomicAdd(&ag[4 * i + 1], hv.y + tv.y);
        atomicAdd(&ag[4 * i + 2], hv.z + tv.z);
        atomicAdd(&ag[4 * i + 3], hv.w + tv.w);
    }
}

// ---------------- weight transpose + fp16 hi/lo split ----------------
__global__ void transpose_split_kernel(const float* __restrict__ W,
                                       int N, int K, int Npad, int Kpad) {
    __shared__ float tile[32][33];
    int tx = threadIdx.x, ty = threadIdx.y;
    int nb = blockIdx.x * 32, kb = blockIdx.y * 32;
    #pragma unroll
    for (int j = 0; j < 4; ++j) {
        int gk = kb + ty + j * 8, gn = nb + tx;
        tile[ty + j * 8][tx] = (gk < K && gn < N) ? W[(size_t)gk * N + gn] : 0.f;
    }
    __syncthreads();
    #pragma unroll
    for (int j = 0; j < 4; ++j) {
        int gn = nb + ty + j * 8, gk = kb + tx;
        if (gn < Npad && gk < Kpad) {
            float v = tile[tx][ty + j * 8];
            __half hi = __float2half_rn(v);
            __half lo = __float2half_rn(v - __half2float(hi));
            g_wth[(size_t)gn * Kpad + gk] = hi;
            g_wtl[(size_t)gn * Kpad + gk] = lo;
        }
    }
}

// ====== shared GEMM machinery ======
#define KT 32
#define WSTRIDE 20   // words per smem row (16 data + 4 pad) = 80 B

__device__ __forceinline__ void mma16f(float* c, const uint32_t* a, const uint32_t* b) {
    asm volatile(
        "mma.sync.aligned.m16n8k16.row.col.f32.f16.f16.f32 "
        "{%0,%1,%2,%3},{%4,%5,%6,%7},{%8,%9},{%0,%1,%2,%3};\n"
        : "+f"(c[0]), "+f"(c[1]), "+f"(c[2]), "+f"(c[3])
        : "r"(a[0]), "r"(a[1]), "r"(a[2]), "r"(a[3]), "r"(b[0]), "r"(b[1]));
}
__device__ __forceinline__ void ldmx4(uint32_t* r, uint32_t addr) {
    asm volatile("ldmatrix.sync.aligned.m8n8.x4.shared.b16 {%0,%1,%2,%3}, [%4];"
        : "=r"(r[0]), "=r"(r[1]), "=r"(r[2]), "=r"(r[3]) : "r"(addr));
}
__device__ __forceinline__ void split4h(float4 f, uint2& hi, uint2& lo) {
    __half h0 = __float2half_rn(f.x), h1 = __float2half_rn(f.y),
           h2 = __float2half_rn(f.z), h3 = __float2half_rn(f.w);
    __half l0 = __float2half_rn(f.x - __half2float(h0)),
           l1 = __float2half_rn(f.y - __half2float(h1)),
           l2 = __float2half_rn(f.z - __half2float(h2)),
           l3 = __float2half_rn(f.w - __half2float(h3));
    __half2 ha = __halves2half2(h0, h1), hb = __halves2half2(h2, h3);
    __half2 la = __halves2half2(l0, l1), lb = __halves2half2(l2, l3);
    hi = make_uint2(*(uint32_t*)&ha, *(uint32_t*)&hb);
    lo = make_uint2(*(uint32_t*)&la, *(uint32_t*)&lb);
}

// inner compute for one k-tile (both GEMMs): 2 k16-steps, ldmatrix + 48 MMAs each
__device__ __forceinline__ void ktile_compute(
        float c[4][4][4], uint32_t sAh, uint32_t sAl, uint32_t sBh, uint32_t sBl,
        int wm, int wn, int a_row, int a_koff, int b_row, int b_koff) {
    #pragma unroll
    for (int ks = 0; ks < 2; ++ks) {
        const int ka = ks * 32 + a_koff;
        const int kb = ks * 32 + b_koff;
        uint32_t afh[4][4], afl[4][4], bfh[4][2], bfl[4][2];
        #pragma unroll
        for (int i = 0; i < 4; ++i) {
            uint32_t ro = (uint32_t)(wm + i * 16 + a_row) * 80 + ka;
            ldmx4(afh[i], sAh + ro);
            ldmx4(afl[i], sAl + ro);
        }
        #pragma unroll
        for (int j2 = 0; j2 < 2; ++j2) {
            uint32_t ro = (uint32_t)(wn + j2 * 16 + b_row) * 80 + kb;
            uint32_t r[4];
            ldmx4(r, sBh + ro);
            bfh[2 * j2][0] = r[0]; bfh[2 * j2][1] = r[1];
            bfh[2 * j2 + 1][0] = r[2]; bfh[2 * j2 + 1][1] = r[3];
            ldmx4(r, sBl + ro);
            bfl[2 * j2][0] = r[0]; bfl[2 * j2][1] = r[1];
            bfl[2 * j2 + 1][0] = r[2]; bfl[2 * j2 + 1][1] = r[3];
        }
        #pragma unroll
        for (int i = 0; i < 4; ++i)
            #pragma unroll
            for (int j = 0; j < 4; ++j) {
                mma16f(c[i][j], afl[i], bfh[j]);
                mma16f(c[i][j], afh[i], bfl[j]);
                mma16f(c[i][j], afh[i], bfh[j]);
            }
    }
}

// ====== GEMM1: t = relu(agg @ W1 + b1), output stored SPLIT fp16 hi/lo ======
__global__ __launch_bounds__(256) void gemm1_kernel(
        const float* __restrict__ A,
        const __half* __restrict__ Wh,
        const __half* __restrict__ Wl,
        const float* __restrict__ bias,
        __half* __restrict__ Th, __half* __restrict__ Tl,
        int M, int N, int K, int Kpad) {
    __shared__ __align__(16) uint32_t Ahs[128 * WSTRIDE];
    __shared__ __align__(16) uint32_t Als[128 * WSTRIDE];
    __shared__ __align__(16) uint32_t Bhs[128 * WSTRIDE];
    __shared__ __align__(16) uint32_t Bls[128 * WSTRIDE];

    const int tid  = threadIdx.x;
    const int lane = tid & 31;
    const int warp = tid >> 5;
    const int g = lane >> 2;
    const int t = lane & 3;
    const int wm = (warp & 1) * 64;
    const int wn = (warp >> 1) * 32;
    const int row0 = blockIdx.y * 128;
    const int col0 = blockIdx.x * 128;

    const uint32_t sAh = smem_u32(Ahs), sAl = smem_u32(Als);
    const uint32_t sBh = smem_u32(Bhs), sBl = smem_u32(Bls);

    const int l8  = lane & 7;
    const int sel = lane >> 3;
    const int a_row  = l8 + ((sel & 1) << 3);
    const int a_koff = ((sel >> 1) << 3) * 2;
    const int b_row  = l8 + ((sel >> 1) << 3);
    const int b_koff = ((sel & 1) << 3) * 2;

    float c[4][4][4] = {};
    float4 ra[4];
    uint4  rb[4];

    const int nk = (K + KT - 1) / KT;

    #pragma unroll
    for (int it = 0; it < 4; ++it) {
        int idx = tid + it * 256;
        {
            int r = idx >> 3, kq = idx & 7;
            int gr = row0 + r, gk = kq * 4;
            ra[it] = (gr < M && gk < K) ? *(const float4*)(A + (size_t)gr * K + gk)
                                        : make_float4(0.f, 0.f, 0.f, 0.f);
        }
        {
            int term = idx >> 9, rem = idx & 511;
            int r = rem >> 2, q = rem & 3;
            rb[it] = *(const uint4*)((term ? Wl : Wh) + (size_t)(col0 + r) * Kpad + q * 8);
        }
    }

    for (int kt = 0; kt < nk; ++kt) {
        #pragma unroll
        for (int it = 0; it < 4; ++it) {
            int idx = tid + it * 256;
            {
                int r = idx >> 3, kq = idx & 7;
                uint2 hi, lo;
                split4h(ra[it], hi, lo);
                *(uint2*)&Ahs[r * WSTRIDE + kq * 2] = hi;
                *(uint2*)&Als[r * WSTRIDE + kq * 2] = lo;
            }
            {
                int term = idx >> 9, rem = idx & 511;
                int r = rem >> 2, q = rem & 3;
                uint32_t* dst = term ? Bls : Bhs;
                *(uint4*)&dst[r * WSTRIDE + q * 4] = rb[it];
            }
        }
        __syncthreads();

        if (kt + 1 < nk) {
            int k0 = (kt + 1) * KT;
            #pragma unroll
            for (int it = 0; it < 4; ++it) {
                int idx = tid + it * 256;
                {
                    int r = idx >> 3, kq = idx & 7;
                    int gr = row0 + r, gk = k0 + kq * 4;
                    ra[it] = (gr < M && gk < K) ? *(const float4*)(A + (size_t)gr * K + gk)
                                                : make_float4(0.f, 0.f, 0.f, 0.f);
                }
                {
                    int term = idx >> 9, rem = idx & 511;
                    int r = rem >> 2, q = rem & 3;
                    rb[it] = *(const uint4*)((term ? Wl : Wh) +
                             (size_t)(col0 + r) * Kpad + k0 + q * 8);
                }
            }
        }

        ktile_compute(c, sAh, sAl, sBh, sBl, wm, wn, a_row, a_koff, b_row, b_koff);
        __syncthreads();
    }

    // ---- epilogue: bias + relu -> split fp16 store into Th/Tl (width TW) ----
    #pragma unroll
    for (int i = 0; i < 4; ++i) {
        int r = row0 + wm + i * 16 + g;
        #pragma unroll
        for (int j = 0; j < 4; ++j) {
            int cc = col0 + wn + j * 8 + 2 * t;
            if (cc >= N) continue;
            float bx = bias[cc], by = bias[cc + 1];
            #pragma unroll
            for (int half = 0; half < 2; ++half) {
                int rr = r + half * 8;
                if (rr >= M) continue;
                float vx = fmaxf(c[i][j][2 * half + 0] + bx, 0.f);
                float vy = fmaxf(c[i][j][2 * half + 1] + by, 0.f);
                __half hx = __float2half_rn(vx), hy = __float2half_rn(vy);
                __half lx = __float2half_rn(vx - __half2float(hx));
                __half ly = __float2half_rn(vy - __half2float(hy));
                __half2 hv = __halves2half2(hx, hy), lv = __halves2half2(lx, ly);
                *(__half2*)&Th[(size_t)rr * TW + cc] = hv;
                *(__half2*)&Tl[(size_t)rr * TW + cc] = lv;
            }
        }
    }
}

// ====== GEMM2: y = t @ W2 (pre-split A, copy staging) + fused BN stats ======
__global__ __launch_bounds__(256) void gemm2_kernel(
        const __half* __restrict__ Ath,
        const __half* __restrict__ Atl,
        const __half* __restrict__ Wh,
        const __half* __restrict__ Wl,
        float* __restrict__ C,
        int M, int N, int Kpad) {
    __shared__ __align__(16) uint32_t Ahs[128 * WSTRIDE];
    __shared__ __align__(16) uint32_t Als[128 * WSTRIDE];
    __shared__ __align__(16) uint32_t Bhs[128 * WSTRIDE];
    __shared__ __align__(16) uint32_t Bls[128 * WSTRIDE];

    const int tid  = threadIdx.x;
    const int lane = tid & 31;
    const int warp = tid >> 5;
    const int g = lane >> 2;
    const int t = lane & 3;
    const int wm = (warp & 1) * 64;
    const int wn = (warp >> 1) * 32;
    const int row0 = blockIdx.y * 128;
    const int col0 = blockIdx.x * 128;

    const uint32_t sAh = smem_u32(Ahs), sAl = smem_u32(Als);
    const uint32_t sBh = smem_u32(Bhs), sBl = smem_u32(Bls);

    const int l8  = lane & 7;
    const int sel = lane >> 3;
    const int a_row  = l8 + ((sel & 1) << 3);
    const int a_koff = ((sel >> 1) << 3) * 2;
    const int b_row  = l8 + ((sel >> 1) << 3);
    const int b_koff = ((sel & 1) << 3) * 2;

    float c[4][4][4] = {};
    uint4 ra[4], rb[4];

    const int nk = Kpad / KT;

    #pragma unroll
    for (int it = 0; it < 4; ++it) {
        int idx = tid + it * 256;
        int term = idx >> 9, rem = idx & 511;
        int r = rem >> 2, q = rem & 3;
        {
            int gr = row0 + r;
            ra[it] = (gr < M) ? *(const uint4*)((term ? Atl : Ath) + (size_t)gr * Kpad + q * 8)
                              : make_uint4(0, 0, 0, 0);
        }
        rb[it] = *(const uint4*)((term ? Wl : Wh) + (size_t)(col0 + r) * Kpad + q * 8);
    }

    for (int kt = 0; kt < nk; ++kt) {
        #pragma unroll
        for (int it = 0; it < 4; ++it) {
            int idx = tid + it * 256;
            int term = idx >> 9, rem = idx & 511;
            int r = rem >> 2, q = rem & 3;
            uint32_t* dstA = term ? Als : Ahs;
            uint32_t* dstB = term ? Bls : Bhs;
            *(uint4*)&dstA[r * WSTRIDE + q * 4] = ra[it];
            *(uint4*)&dstB[r * WSTRIDE + q * 4] = rb[it];
        }
        __syncthreads();

        if (kt + 1 < nk) {
            int k0 = (kt + 1) * KT;
            #pragma unroll
            for (int it = 0; it < 4; ++it) {
                int idx = tid + it * 256;
                int term = idx >> 9, rem = idx & 511;
                int r = rem >> 2, q = rem & 3;
                {
                    int gr = row0 + r;
                    ra[it] = (gr < M) ? *(const uint4*)((term ? Atl : Ath) +
                                        (size_t)gr * Kpad + k0 + q * 8)
                                      : make_uint4(0, 0, 0, 0);
                }
                rb[it] = *(const uint4*)((term ? Wl : Wh) +
                         (size_t)(col0 + r) * Kpad + k0 + q * 8);
            }
        }

        ktile_compute(c, sAh, sAl, sBh, sBl, wm, wn, a_row, a_koff, b_row, b_koff);
        __syncthreads();
    }

    // ---- fused BN stats (bias cancels in BN; rows>=M are exact 0) ----
    #pragma unroll
    for (int j = 0; j < 4; ++j) {
        float s0 = 0.f, q0 = 0.f, s1 = 0.f, q1 = 0.f;
        #pragma unroll
        for (int i = 0; i < 4; ++i) {
            float v0 = c[i][j][0], v1 = c[i][j][1];
            float v2 = c[i][j][2], v3 = c[i][j][3];
            s0 += v0 + v2; q0 += v0 * v0 + v2 * v2;
            s1 += v1 + v3; q1 += v1 * v1 + v3 * v3;
        }
        #pragma unroll
        for (int m = 4; m < 32; m <<= 1) {
            s0 += __shfl_xor_sync(0xFFFFFFFFu, s0, m);
            q0 += __shfl_xor_sync(0xFFFFFFFFu, q0, m);
            s1 += __shfl_xor_sync(0xFFFFFFFFu, s1, m);
            q1 += __shfl_xor_sync(0xFFFFFFFFu, q1, m);
        }
        if (lane < 4) {
            int cc = col0 + wn + j * 8 + 2 * t;
            if (cc < EMB) {
                atomicAdd(&g_stats[cc], s0);
                atomicAdd(&g_stats[EMB + cc], q0);
            }
            if (cc + 1 < EMB) {
                atomicAdd(&g_stats[cc + 1], s1);
                atomicAdd(&g_stats[EMB + cc + 1], q1);
            }
        }
    }
    // store y (no bias)
    #pragma unroll
    for (int i = 0; i < 4; ++i) {
        int r = row0 + wm + i * 16 + g;
        #pragma unroll
        for (int j = 0; j < 4; ++j) {
            int cc = col0 + wn + j * 8 + 2 * t;
            if (cc >= N) continue;
            if (r < M)
                *(float2*)&C[(size_t)r * N + cc] = make_float2(c[i][j][0], c[i][j][1]);
            int r2 = r + 8;
            if (r2 < M)
                *(float2*)&C[(size_t)r2 * N + cc] = make_float2(c[i][j][2], c[i][j][3]);
        }
    }
}

// ---------------- BN apply (uncentered stats); fused agg init / pooling ----------------
__global__ void bn_apply_kernel(const float* __restrict__ X,
                                const float* __restrict__ gamma,
                                const float* __restrict__ beta,
                                const int* __restrict__ batch,
                                float* __restrict__ out,
                                int l, int doRelu, int doAgg, int doPool) {
    int idx = blockIdx.x * blockDim.x + threadIdx.x;
    if (idx >= N_NODES * EMB) return;
    int c = idx % EMB;
    float mu  = g_stats[c] * (1.f / N_NODES);
    float var = fmaxf(g_stats[EMB + c] * (1.f / N_NODES) - mu * mu, 0.f);
    float sc = rsqrtf(var + BN_EPS) * gamma[l * EMB + c];
    float v = (X[idx] - mu) * sc + beta[l * EMB + c];
    if (doRelu) v = fmaxf(v, 0.f);
    if (doPool) {
        int i = idx / EMB;
        atomicAdd(&out[(size_t)batch[i] * EMB + c], v);
    } else {
        g_h[idx] = v;
        if (doAgg) g_agg[idx] = v + g_tab[c];
    }
}

// ---------------- pooling ----------------
__global__ void pool_zero_kernel(float* __restrict__ out) {
    int idx = blockIdx.x * blockDim.x + threadIdx.x;
    if (idx < NUM_GRAPHS) g_counts[idx] = 0.f;
    if (idx < NUM_GRAPHS * EMB) out[idx] = 0.f;
}
__global__ void pool_count_kernel(const int* __restrict__ batch) {
    int i = blockIdx.x * blockDim.x + threadIdx.x;
    if (i >= N_NODES) return;
    atomicAdd(&g_counts[batch[i]], 1.f);
}
__global__ void pool_div_kernel(float* __restrict__ out) {
    int idx = blockIdx.x * blockDim.x + threadIdx.x;
    if (idx >= NUM_GRAPHS * EMB) return;
    out[idx] /= fmaxf(g_counts[idx / EMB], 1.f);
}

// ---------------- launch ----------------
extern "C" void kernel_launch(void* const* d_in, const int* in_sizes, int n_in,
                              void* d_out, int out_size) {
    const int*   x        = (const int*)d_in[0];
    const int*   edge_idx = (const int*)d_in[1];
    const int*   edge_att = (const int*)d_in[2];
    const int*   batch    = (const int*)d_in[3];
    const float* x_emb1   = (const float*)d_in[4];
    const float* x_emb2   = (const float*)d_in[5];
    const float* edge_e1  = (const float*)d_in[6];
    const float* edge_e2  = (const float*)d_in[7];
    const float* W1       = (const float*)d_in[8];
    const float* b1       = (const float*)d_in[9];
    const float* W2       = (const float*)d_in[10];
    const float* b2       = (const float*)d_in[11];
    const float* gamma    = (const float*)d_in[12];
    const float* beta     = (const float*)d_in[13];
    float* out = (float*)d_out;
    (void)b2;  // b2 cancels inside BatchNorm

    const int NE = N_NODES * EMB;
    const int TPB = 256;

    init_h_kernel<<<(NE + TPB - 1) / TPB, TPB>>>(x, x_emb1, x_emb2);

    float *p_agg;
    __half *p_wh, *p_wl, *p_th, *p_tl;
    cudaGetSymbolAddress((void**)&p_agg, g_agg);
    cudaGetSymbolAddress((void**)&p_wh, g_wth);
    cudaGetSymbolAddress((void**)&p_wl, g_wtl);
    cudaGetSymbolAddress((void**)&p_th, g_th);
    cudaGetSymbolAddress((void**)&p_tl, g_tl);

    const int MT = (N_NODES + 127) / 128;   // 782
    dim3 tb(32, 8);
    dim3 tr1(640 / 32, 320 / 32);   // GEMM1 weights: Npad=640, Kpad=320
    dim3 tr2(384 / 32, 640 / 32);   // GEMM2 weights: Npad=384, Kpad=640
    dim3 gg1(5, MT), gg2(3, MT);

    // layer-0 aggregation init
    build_tab_kernel<<<(9 * EMB + TPB - 1) / TPB, TPB>>>(edge_e1, edge_e2, 0);
    init_agg_kernel<<<(NE + TPB - 1) / TPB, TPB>>>();

    for (int l = 0; l < NUM_LAYER; ++l) {
        zero_stats_kernel<<<3, 256>>>();
        scatter_edges_kernel<<<(N_EDGES + 7) / 8, 256>>>(edge_idx, edge_att);

        // t = relu(agg @ W1[l] + b1[l])  -> split fp16 (g_th, g_tl), width TW=640
        transpose_split_kernel<<<tr1, tb>>>(W1 + (size_t)l * EMB * EMB2,
                                            EMB2, EMB, 640, 320);
        gemm1_kernel<<<gg1, 256>>>(p_agg, p_wh, p_wl, b1 + l * EMB2,
                                   p_th, p_tl, N_NODES, EMB2, EMB, 320);
        // y = t @ W2[l]  (bias cancels in BN; stats fused)
        transpose_split_kernel<<<tr2, tb>>>(W2 + (size_t)l * EMB2 * EMB,
                                            EMB, EMB2, 384, 640);
        gemm2_kernel<<<gg2, 256>>>(p_th, p_tl, p_wh, p_wl, p_agg,
                                   N_NODES, EMB, 640);

        int last = (l == NUM_LAYER - 1);
        if (!last) {
            build_tab_kernel<<<(9 * EMB + TPB - 1) / TPB, TPB>>>(edge_e1, edge_e2, l + 1);
            bn_apply_kernel<<<(NE + TPB - 1) / TPB, TPB>>>(p_agg, gamma, beta,
                                                           batch, out, l, 1, 1, 0);
        } else {
            pool_zero_kernel<<<(NUM_GRAPHS * EMB + TPB - 1) / TPB, TPB>>>(out);
            pool_count_kernel<<<(N_NODES + TPB - 1) / TPB, TPB>>>(batch);
            bn_apply_kernel<<<(NE + TPB - 1) / TPB, TPB>>>(p_agg, gamma, beta,
                                                           batch, out, l, 0, 0, 1);
            pool_div_kernel<<<(NUM_GRAPHS * EMB + TPB - 1) / TPB, TPB>>>(out);
        }
    }
}

// round 11
// speedup vs baseline: 1.0638x; 1.0638x over previous
#include <cuda_runtime.h>
#include <cuda_fp16.h>
#include <math.h>
#include <stdint.h>

#define N_NODES   100000
#define N_EDGES   200000
#define EMB       300
#define EMB2      600
#define NUM_LAYER 5
#define NUM_GRAPHS 5000
#define BN_EPS    1e-5f

// ---------------- device scratch (allocation-free) ----------------
__device__ __align__(16) float g_h[N_NODES * EMB];
__device__ __align__(16) float g_agg[N_NODES * EMB];
__device__ __align__(16) float g_t[N_NODES * EMB2];
__device__ __align__(16) float g_tab[9 * EMB];
__device__ float g_stats[2 * EMB];     // [0:EMB) sum(y), [EMB:2EMB) sum(y^2)
__device__ float g_counts[NUM_GRAPHS];
// transposed + split weights (fp16 hi/lo), zero-padded: max 384x640 = 245760
__device__ __align__(16) __half g_wth[245760];
__device__ __align__(16) __half g_wtl[245760];

__device__ __forceinline__ uint32_t smem_u32(const void* p) {
    uint32_t a;
    asm("{ .reg .u64 t; cvta.to.shared.u64 t, %1; cvt.u32.u64 %0, t; }" : "=r"(a) : "l"(p));
    return a;
}

// ---------------- h0 = x_emb1[x0] + x_emb2[x1] ----------------
__global__ void init_h_kernel(const int* __restrict__ x,
                              const float* __restrict__ e1,
                              const float* __restrict__ e2) {
    int idx = blockIdx.x * blockDim.x + threadIdx.x;
    if (idx >= N_NODES * EMB) return;
    int i = idx / EMB, c = idx - i * EMB;
    int a = x[2 * i], b = x[2 * i + 1];
    g_h[idx] = e1[a * EMB + c] + e2[b * EMB + c];
}

// ---------------- per-layer eemb table (does NOT touch g_stats) ----------------
__global__ void build_tab_kernel(const float* __restrict__ e1,
                                 const float* __restrict__ e2, int l) {
    int idx = blockIdx.x * blockDim.x + threadIdx.x;
    if (idx >= 9 * EMB) return;
    int t = idx / EMB, c = idx - t * EMB;
    int a = t / 3, b = t - a * 3;
    g_tab[idx] = e1[(l * 6 + a) * EMB + c] + e2[(l * 3 + b) * EMB + c];
}

// zero stats, launched at the top of each layer (before gemm2 accumulates)
__global__ void zero_stats_kernel() {
    int idx = blockIdx.x * blockDim.x + threadIdx.x;
    if (idx < 2 * EMB) g_stats[idx] = 0.f;
}

// ---------------- agg = h + tab[0]  (first layer only) ----------------
__global__ void init_agg_kernel() {
    int idx = blockIdx.x * blockDim.x + threadIdx.x;
    if (idx >= N_NODES * EMB) return;
    g_agg[idx] = g_h[idx] + g_tab[idx % EMB];
}

// ---------------- edge scatter: agg[dst] += h[src] + tab[attr] ----------------
__global__ __launch_bounds__(256) void scatter_edges_kernel(
        const int* __restrict__ ei, const int* __restrict__ ea) {
    int e = blockIdx.x * 8 + (threadIdx.x >> 5);
    if (e >= N_EDGES) return;
    int lane = threadIdx.x & 31;
    int src = ei[e];
    int dst = ei[N_EDGES + e];
    int t = ea[2 * e] * 3 + ea[2 * e + 1];
    const float4* hs = (const float4*)(g_h + (size_t)src * EMB);
    const float4* tb = (const float4*)(g_tab + t * EMB);
    float* ag = g_agg + (size_t)dst * EMB;
    #pragma unroll
    for (int i = lane; i < EMB / 4; i += 32) {
        float4 hv = hs[i];
        float4 tv = tb[i];
        atomicAdd(&ag[4 * i + 0], hv.x + tv.x);
        atomicAdd(&ag[4 * i + 1], hv.y + tv.y);
        atomicAdd(&ag[4 * i + 2], hv.z + tv.z);
        atomicAdd(&ag[4 * i + 3], hv.w + tv.w);
    }
}

// ---------------- weight transpose + fp16 hi/lo split ----------------
__global__ void transpose_split_kernel(const float* __restrict__ W,
                                       int N, int K, int Npad, int Kpad) {
    __shared__ float tile[32][33];
    int tx = threadIdx.x, ty = threadIdx.y;
    int nb = blockIdx.x * 32, kb = blockIdx.y * 32;
    #pragma unroll
    for (int j = 0; j < 4; ++j) {
        int gk = kb + ty + j * 8, gn = nb + tx;
        tile[ty + j * 8][tx] = (gk < K && gn < N) ? W[(size_t)gk * N + gn] : 0.f;
    }
    __syncthreads();
    #pragma unroll
    for (int j = 0; j < 4; ++j) {
        int gn = nb + ty + j * 8, gk = kb + tx;
        if (gn < Npad && gk < Kpad) {
            float v = tile[tx][ty + j * 8];
            __half hi = __float2half_rn(v);
            __half lo = __float2half_rn(v - __half2float(hi));
            g_wth[(size_t)gn * Kpad + gk] = hi;
            g_wtl[(size_t)gn * Kpad + gk] = lo;
        }
    }
}

// ====== 3-term split-fp16 tensor GEMM + optional fused BN stats ======
// Block 128x128, K-tile 32, 8 warps x (64x32), mma.m16n8k16.f16, ldmatrix.
#define KT 32
#define WSTRIDE 20   // words per smem row (16 data + 4 pad) = 80 B

__device__ __forceinline__ void mma16f(float* c, const uint32_t* a, const uint32_t* b) {
    asm volatile(
        "mma.sync.aligned.m16n8k16.row.col.f32.f16.f16.f32 "
        "{%0,%1,%2,%3},{%4,%5,%6,%7},{%8,%9},{%0,%1,%2,%3};\n"
        : "+f"(c[0]), "+f"(c[1]), "+f"(c[2]), "+f"(c[3])
        : "r"(a[0]), "r"(a[1]), "r"(a[2]), "r"(a[3]), "r"(b[0]), "r"(b[1]));
}
__device__ __forceinline__ void ldmx4(uint32_t* r, uint32_t addr) {
    asm volatile("ldmatrix.sync.aligned.m8n8.x4.shared.b16 {%0,%1,%2,%3}, [%4];"
        : "=r"(r[0]), "=r"(r[1]), "=r"(r[2]), "=r"(r[3]) : "r"(addr));
}

__device__ __forceinline__ void split4h(float4 f, uint2& hi, uint2& lo) {
    __half h0 = __float2half_rn(f.x), h1 = __float2half_rn(f.y),
           h2 = __float2half_rn(f.z), h3 = __float2half_rn(f.w);
    __half l0 = __float2half_rn(f.x - __half2float(h0)),
           l1 = __float2half_rn(f.y - __half2float(h1)),
           l2 = __float2half_rn(f.z - __half2float(h2)),
           l3 = __float2half_rn(f.w - __half2float(h3));
    __half2 ha = __halves2half2(h0, h1), hb = __halves2half2(h2, h3);
    __half2 la = __halves2half2(l0, l1), lb = __halves2half2(l2, l3);
    hi = make_uint2(*(uint32_t*)&ha, *(uint32_t*)&hb);
    lo = make_uint2(*(uint32_t*)&la, *(uint32_t*)&lb);
}

// doStats: skip bias (BN-invariant), accumulate per-column sum/sumsq into g_stats.
__global__ __launch_bounds__(256) void gemm_fp16x3_kernel(
        const float* __restrict__ A,
        const __half* __restrict__ Wh,
        const __half* __restrict__ Wl,
        const float* __restrict__ bias, float* __restrict__ C,
        int M, int N, int K, int Kpad, int doRelu, int doStats) {
    __shared__ __align__(16) uint32_t Ah[128 * WSTRIDE];
    __shared__ __align__(16) uint32_t Al[128 * WSTRIDE];
    __shared__ __align__(16) uint32_t Bh[128 * WSTRIDE];
    __shared__ __align__(16) uint32_t Bl[128 * WSTRIDE];

    const int tid  = threadIdx.x;
    const int lane = tid & 31;
    const int warp = tid >> 5;
    const int g = lane >> 2;
    const int t = lane & 3;
    const int wm = (warp & 1) * 64;
    const int wn = (warp >> 1) * 32;
    const int row0 = blockIdx.y * 128;
    const int col0 = blockIdx.x * 128;

    const uint32_t sAh = smem_u32(Ah), sAl = smem_u32(Al);
    const uint32_t sBh = smem_u32(Bh), sBl = smem_u32(Bl);

    // ldmatrix lane selectors
    const int l8  = lane & 7;
    const int sel = lane >> 3;
    const int a_row  = l8 + ((sel & 1) << 3);
    const int a_koff = ((sel >> 1) << 3) * 2;
    const int b_row  = l8 + ((sel >> 1) << 3);
    const int b_koff = ((sel & 1) << 3) * 2;

    float c[4][4][4] = {};
    float4 ra[4];
    uint4  rb[4];

    const int nk = (K + KT - 1) / KT;

    // ---- prefetch tile 0 ----
    #pragma unroll
    for (int it = 0; it < 4; ++it) {
        int idx = tid + it * 256;
        {
            int r = idx >> 3, kq = idx & 7;
            int gr = row0 + r, gk = kq * 4;
            ra[it] = (gr < M && gk < K) ? *(const float4*)(A + (size_t)gr * K + gk)
                                        : make_float4(0.f, 0.f, 0.f, 0.f);
        }
        {
            int term = idx >> 9, rem = idx & 511;
            int r = rem >> 2, q = rem & 3;
            rb[it] = *(const uint4*)((term ? Wl : Wh) + (size_t)(col0 + r) * Kpad + q * 8);
        }
    }

    for (int kt = 0; kt < nk; ++kt) {
        // ---- store staged tile to smem ----
        #pragma unroll
        for (int it = 0; it < 4; ++it) {
            int idx = tid + it * 256;
            {
                int r = idx >> 3, kq = idx & 7;
                uint2 hi, lo;
                split4h(ra[it], hi, lo);
                *(uint2*)&Ah[r * WSTRIDE + kq * 2] = hi;
                *(uint2*)&Al[r * WSTRIDE + kq * 2] = lo;
            }
            {
                int term = idx >> 9, rem = idx & 511;
                int r = rem >> 2, q = rem & 3;
                uint32_t* dst = term ? Bl : Bh;
                *(uint4*)&dst[r * WSTRIDE + q * 4] = rb[it];
            }
        }
        __syncthreads();

        // ---- prefetch next tile ----
        if (kt + 1 < nk) {
            int k0 = (kt + 1) * KT;
            #pragma unroll
            for (int it = 0; it < 4; ++it) {
                int idx = tid + it * 256;
                {
                    int r = idx >> 3, kq = idx & 7;
                    int gr = row0 + r, gk = k0 + kq * 4;
                    ra[it] = (gr < M && gk < K) ? *(const float4*)(A + (size_t)gr * K + gk)
                                                : make_float4(0.f, 0.f, 0.f, 0.f);
                }
                {
                    int term = idx >> 9, rem = idx & 511;
                    int r = rem >> 2, q = rem & 3;
                    rb[it] = *(const uint4*)((term ? Wl : Wh) +
                             (size_t)(col0 + r) * Kpad + k0 + q * 8);
                }
            }
        }

        // ---- compute: 2 k16-steps, ldmatrix + 48 MMAs each ----
        #pragma unroll
        for (int ks = 0; ks < 2; ++ks) {
            const int ka = ks * 32 + a_koff;
            const int kb = ks * 32 + b_koff;
            uint32_t afh[4][4], afl[4][4], bfh[4][2], bfl[4][2];
            #pragma unroll
            for (int i = 0; i < 4; ++i) {
                uint32_t ro = (uint32_t)(wm + i * 16 + a_row) * 80 + ka;
                ldmx4(afh[i], sAh + ro);
                ldmx4(afl[i], sAl + ro);
            }
            #pragma unroll
            for (int j2 = 0; j2 < 2; ++j2) {
                uint32_t ro = (uint32_t)(wn + j2 * 16 + b_row) * 80 + kb;
                uint32_t r[4];
                ldmx4(r, sBh + ro);
                bfh[2 * j2][0] = r[0]; bfh[2 * j2][1] = r[1];
                bfh[2 * j2 + 1][0] = r[2]; bfh[2 * j2 + 1][1] = r[3];
                ldmx4(r, sBl + ro);
                bfl[2 * j2][0] = r[0]; bfl[2 * j2][1] = r[1];
                bfl[2 * j2 + 1][0] = r[2]; bfl[2 * j2 + 1][1] = r[3];
            }
            #pragma unroll
            for (int i = 0; i < 4; ++i)
                #pragma unroll
                for (int j = 0; j < 4; ++j) {
                    mma16f(c[i][j], afl[i], bfh[j]);
                    mma16f(c[i][j], afh[i], bfl[j]);
                    mma16f(c[i][j], afh[i], bfh[j]);
                }
        }
        __syncthreads();
    }

    if (doStats) {
        // ---- per-column sum & sumsq (bias cancels in BN; rows>=M are exact 0) ----
        #pragma unroll
        for (int j = 0; j < 4; ++j) {
            float s0 = 0.f, q0 = 0.f, s1 = 0.f, q1 = 0.f;
            #pragma unroll
            for (int i = 0; i < 4; ++i) {
                float v0 = c[i][j][0], v1 = c[i][j][1];
                float v2 = c[i][j][2], v3 = c[i][j][3];
                s0 += v0 + v2; q0 += v0 * v0 + v2 * v2;
                s1 += v1 + v3; q1 += v1 * v1 + v3 * v3;
            }
            #pragma unroll
            for (int m = 4; m < 32; m <<= 1) {
                s0 += __shfl_xor_sync(0xFFFFFFFFu, s0, m);
                q0 += __shfl_xor_sync(0xFFFFFFFFu, q0, m);
                s1 += __shfl_xor_sync(0xFFFFFFFFu, s1, m);
                q1 += __shfl_xor_sync(0xFFFFFFFFu, q1, m);
            }
            if (lane < 4) {
                int cc = col0 + wn + j * 8 + 2 * t;
                if (cc < EMB) {
                    atomicAdd(&g_stats[cc], s0);
                    atomicAdd(&g_stats[EMB + cc], q0);
                }
                if (cc + 1 < EMB) {
                    atomicAdd(&g_stats[cc + 1], s1);
                    atomicAdd(&g_stats[EMB + cc + 1], q1);
                }
            }
        }
        // store WITHOUT bias
        #pragma unroll
        for (int i = 0; i < 4; ++i) {
            int r = row0 + wm + i * 16 + g;
            #pragma unroll
            for (int j = 0; j < 4; ++j) {
                int cc = col0 + wn + j * 8 + 2 * t;
                if (cc >= N) continue;
                if (r < M)
                    *(float2*)&C[(size_t)r * N + cc] = make_float2(c[i][j][0], c[i][j][1]);
                int r2 = r + 8;
                if (r2 < M)
                    *(float2*)&C[(size_t)r2 * N + cc] = make_float2(c[i][j][2], c[i][j][3]);
            }
        }
    } else {
        // ---- bias + optional relu ----
        #pragma unroll
        for (int i = 0; i < 4; ++i) {
            int r = row0 + wm + i * 16 + g;
            #pragma unroll
            for (int j = 0; j < 4; ++j) {
                int cc = col0 + wn + j * 8 + 2 * t;
                if (cc >= N) continue;
                float bx = bias[cc], by = bias[cc + 1];
                if (r < M) {
                    float2 v = make_float2(c[i][j][0] + bx, c[i][j][1] + by);
                    if (doRelu) { v.x = fmaxf(v.x, 0.f); v.y = fmaxf(v.y, 0.f); }
                    *(float2*)&C[(size_t)r * N + cc] = v;
                }
                int r2 = r + 8;
                if (r2 < M) {
                    float2 v = make_float2(c[i][j][2] + bx, c[i][j][3] + by);
                    if (doRelu) { v.x = fmaxf(v.x, 0.f); v.y = fmaxf(v.y, 0.f); }
                    *(float2*)&C[(size_t)r2 * N + cc] = v;
                }
            }
        }
    }
}

// ---------------- BN apply (uncentered stats); fused agg init / pooling ----------------
__global__ void bn_apply_kernel(const float* __restrict__ X,
                                const float* __restrict__ gamma,
                                const float* __restrict__ beta,
                                const int* __restrict__ batch,
                                float* __restrict__ out,
                                int l, int doRelu, int doAgg, int doPool) {
    int idx = blockIdx.x * blockDim.x + threadIdx.x;
    if (idx >= N_NODES * EMB) return;
    int c = idx % EMB;
    float mu  = g_stats[c] * (1.f / N_NODES);
    float var = fmaxf(g_stats[EMB + c] * (1.f / N_NODES) - mu * mu, 0.f);
    float sc = rsqrtf(var + BN_EPS) * gamma[l * EMB + c];
    float v = (X[idx] - mu) * sc + beta[l * EMB + c];
    if (doRelu) v = fmaxf(v, 0.f);
    if (doPool) {
        int i = idx / EMB;
        atomicAdd(&out[(size_t)batch[i] * EMB + c], v);
    } else {
        g_h[idx] = v;
        if (doAgg) g_agg[idx] = v + g_tab[c];
    }
}

// ---------------- pooling ----------------
__global__ void pool_zero_kernel(float* __restrict__ out) {
    int idx = blockIdx.x * blockDim.x + threadIdx.x;
    if (idx < NUM_GRAPHS) g_counts[idx] = 0.f;
    if (idx < NUM_GRAPHS * EMB) out[idx] = 0.f;
}
__global__ void pool_count_kernel(const int* __restrict__ batch) {
    int i = blockIdx.x * blockDim.x + threadIdx.x;
    if (i >= N_NODES) return;
    atomicAdd(&g_counts[batch[i]], 1.f);
}
__global__ void pool_div_kernel(float* __restrict__ out) {
    int idx = blockIdx.x * blockDim.x + threadIdx.x;
    if (idx >= NUM_GRAPHS * EMB) return;
    out[idx] /= fmaxf(g_counts[idx / EMB], 1.f);
}

// ---------------- launch ----------------
extern "C" void kernel_launch(void* const* d_in, const int* in_sizes, int n_in,
                              void* d_out, int out_size) {
    const int*   x        = (const int*)d_in[0];
    const int*   edge_idx = (const int*)d_in[1];
    const int*   edge_att = (const int*)d_in[2];
    const int*   batch    = (const int*)d_in[3];
    const float* x_emb1   = (const float*)d_in[4];
    const float* x_emb2   = (const float*)d_in[5];
    const float* edge_e1  = (const float*)d_in[6];
    const float* edge_e2  = (const float*)d_in[7];
    const float* W1       = (const float*)d_in[8];
    const float* b1       = (const float*)d_in[9];
    const float* W2       = (const float*)d_in[10];
    const float* b2       = (const float*)d_in[11];
    const float* gamma    = (const float*)d_in[12];
    const float* beta     = (const float*)d_in[13];
    float* out = (float*)d_out;
    (void)b2;  // b2 cancels inside BatchNorm

    const int NE = N_NODES * EMB;
    const int TPB = 256;

    init_h_kernel<<<(NE + TPB - 1) / TPB, TPB>>>(x, x_emb1, x_emb2);

    float *p_agg, *p_t;
    __half *p_wh, *p_wl;
    cudaGetSymbolAddress((void**)&p_agg, g_agg);
    cudaGetSymbolAddress((void**)&p_t, g_t);
    cudaGetSymbolAddress((void**)&p_wh, g_wth);
    cudaGetSymbolAddress((void**)&p_wl, g_wtl);

    const int MT = (N_NODES + 127) / 128;   // 782
    dim3 tb(32, 8);
    dim3 tr1(640 / 32, 320 / 32);   // GEMM1 weights: Npad=640, Kpad=320
    dim3 tr2(384 / 32, 640 / 32);   // GEMM2 weights: Npad=384, Kpad=640
    dim3 gg1(5, MT), gg2(3, MT);

    // layer-0 aggregation init
    build_tab_kernel<<<(9 * EMB + TPB - 1) / TPB, TPB>>>(edge_e1, edge_e2, 0);
    init_agg_kernel<<<(NE + TPB - 1) / TPB, TPB>>>();

    for (int l = 0; l < NUM_LAYER; ++l) {
        zero_stats_kernel<<<3, 256>>>();   // BEFORE gemm2 accumulates stats
        scatter_edges_kernel<<<(N_EDGES + 7) / 8, 256>>>(edge_idx, edge_att);

        // t = relu(agg @ W1[l] + b1[l])   [N, 600]
        transpose_split_kernel<<<tr1, tb>>>(W1 + (size_t)l * EMB * EMB2,
                                            EMB2, EMB, 640, 320);
        gemm_fp16x3_kernel<<<gg1, 256>>>(p_agg, p_wh, p_wl,
                                         b1 + l * EMB2, p_t,
                                         N_NODES, EMB2, EMB, 320, 1, 0);
        // y = t @ W2[l]   [N, 300]  (bias cancels in BN; stats fused)
        transpose_split_kernel<<<tr2, tb>>>(W2 + (size_t)l * EMB2 * EMB,
                                            EMB, EMB2, 384, 640);
        gemm_fp16x3_kernel<<<gg2, 256>>>(p_t, p_wh, p_wl,
                                         b2, p_agg,
                                         N_NODES, EMB, EMB2, 640, 0, 1);

        int last = (l == NUM_LAYER - 1);
        if (!last) {
            // build next layer's table (no stats touch) BEFORE fused apply+agg
            build_tab_kernel<<<(9 * EMB + TPB - 1) / TPB, TPB>>>(edge_e1, edge_e2, l + 1);
            bn_apply_kernel<<<(NE + TPB - 1) / TPB, TPB>>>(p_agg, gamma, beta,
                                                           batch, out, l, 1, 1, 0);
        } else {
            pool_zero_kernel<<<(NUM_GRAPHS * EMB + TPB - 1) / TPB, TPB>>>(out);
            pool_count_kernel<<<(N_NODES + TPB - 1) / TPB, TPB>>>(batch);
            bn_apply_kernel<<<(NE + TPB - 1) / TPB, TPB>>>(p_agg, gamma, beta,
                                                           batch, out, l, 0, 0, 1);
            pool_div_kernel<<<(NUM_GRAPHS * EMB + TPB - 1) / TPB, TPB>>>(out);
        }
    }
}

// round 12
// speedup vs baseline: 1.1464x; 1.0776x over previous
#include <cuda_runtime.h>
#include <cuda_fp16.h>
#include <math.h>
#include <stdint.h>

#define N_NODES   100000
#define N_EDGES   200000
#define EMB       300
#define EMB2      600
#define NUM_LAYER 5
#define NUM_GRAPHS 5000
#define BN_EPS    1e-5f

// ---------------- device scratch (allocation-free) ----------------
__device__ __align__(16) float g_h[N_NODES * EMB];
__device__ __align__(16) float g_agg[N_NODES * EMB];
__device__ __align__(16) float g_t[N_NODES * EMB2];
__device__ __align__(16) float g_tab[9 * EMB];
__device__ float g_stats[2 * EMB];     // [0:EMB) sum(y), [EMB:2EMB) sum(y^2)
__device__ float g_counts[NUM_GRAPHS];
// transposed + split weights (fp16 hi/lo), zero-padded: max 384x640 = 245760
__device__ __align__(16) __half g_wth[245760];
__device__ __align__(16) __half g_wtl[245760];

__device__ __forceinline__ uint32_t smem_u32(const void* p) {
    uint32_t a;
    asm("{ .reg .u64 t; cvta.to.shared.u64 t, %1; cvt.u32.u64 %0, t; }" : "=r"(a) : "l"(p));
    return a;
}

// ---------------- h0 = x_emb1[x0] + x_emb2[x1] ----------------
__global__ void init_h_kernel(const int* __restrict__ x,
                              const float* __restrict__ e1,
                              const float* __restrict__ e2) {
    int idx = blockIdx.x * blockDim.x + threadIdx.x;
    if (idx >= N_NODES * EMB) return;
    int i = idx / EMB, c = idx - i * EMB;
    int a = x[2 * i], b = x[2 * i + 1];
    g_h[idx] = e1[a * EMB + c] + e2[b * EMB + c];
}

// ---------------- per-layer eemb table (does NOT touch g_stats) ----------------
__global__ void build_tab_kernel(const float* __restrict__ e1,
                                 const float* __restrict__ e2, int l) {
    int idx = blockIdx.x * blockDim.x + threadIdx.x;
    if (idx >= 9 * EMB) return;
    int t = idx / EMB, c = idx - t * EMB;
    int a = t / 3, b = t - a * 3;
    g_tab[idx] = e1[(l * 6 + a) * EMB + c] + e2[(l * 3 + b) * EMB + c];
}

// zero stats, launched at the top of each layer (before gemm2 accumulates)
__global__ void zero_stats_kernel() {
    int idx = blockIdx.x * blockDim.x + threadIdx.x;
    if (idx < 2 * EMB) g_stats[idx] = 0.f;
}

// ---------------- agg = h + tab[0]  (first layer only) ----------------
__global__ void init_agg_kernel() {
    int idx = blockIdx.x * blockDim.x + threadIdx.x;
    if (idx >= N_NODES * EMB) return;
    g_agg[idx] = g_h[idx] + g_tab[idx % EMB];
}

// ---------------- edge scatter: agg[dst] += h[src] + tab[attr] ----------------
__global__ __launch_bounds__(256) void scatter_edges_kernel(
        const int* __restrict__ ei, const int* __restrict__ ea) {
    int e = blockIdx.x * 8 + (threadIdx.x >> 5);
    if (e >= N_EDGES) return;
    int lane = threadIdx.x & 31;
    int src = ei[e];
    int dst = ei[N_EDGES + e];
    int t = ea[2 * e] * 3 + ea[2 * e + 1];
    const float4* hs = (const float4*)(g_h + (size_t)src * EMB);
    const float4* tb = (const float4*)(g_tab + t * EMB);
    float* ag = g_agg + (size_t)dst * EMB;
    #pragma unroll
    for (int i = lane; i < EMB / 4; i += 32) {
        float4 hv = hs[i];
        float4 tv = tb[i];
        atomicAdd(&ag[4 * i + 0], hv.x + tv.x);
        atomicAdd(&ag[4 * i + 1], hv.y + tv.y);
        atomicAdd(&ag[4 * i + 2], hv.z + tv.z);
        atomicAdd(&ag[4 * i + 3], hv.w + tv.w);
    }
}

// ---------------- weight transpose + fp16 hi/lo split ----------------
__global__ void transpose_split_kernel(const float* __restrict__ W,
                                       int N, int K, int Npad, int Kpad) {
    __shared__ float tile[32][33];
    int tx = threadIdx.x, ty = threadIdx.y;
    int nb = blockIdx.x * 32, kb = blockIdx.y * 32;
    #pragma unroll
    for (int j = 0; j < 4; ++j) {
        int gk = kb + ty + j * 8, gn = nb + tx;
        tile[ty + j * 8][tx] = (gk < K && gn < N) ? W[(size_t)gk * N + gn] : 0.f;
    }
    __syncthreads();
    #pragma unroll
    for (int j = 0; j < 4; ++j) {
        int gn = nb + ty + j * 8, gk = kb + tx;
        if (gn < Npad && gk < Kpad) {
            float v = tile[tx][ty + j * 8];
            __half hi = __float2half_rn(v);
            __half lo = __float2half_rn(v - __half2float(hi));
            g_wth[(size_t)gn * Kpad + gk] = hi;
            g_wtl[(size_t)gn * Kpad + gk] = lo;
        }
    }
}

// ====== shared GEMM primitives ======
#define KT 32
#define WSTRIDE 20   // words per smem row (16 data + 4 pad) = 80 B

__device__ __forceinline__ void mma16f(float* c, const uint32_t* a, const uint32_t* b) {
    asm volatile(
        "mma.sync.aligned.m16n8k16.row.col.f32.f16.f16.f32 "
        "{%0,%1,%2,%3},{%4,%5,%6,%7},{%8,%9},{%0,%1,%2,%3};\n"
        : "+f"(c[0]), "+f"(c[1]), "+f"(c[2]), "+f"(c[3])
        : "r"(a[0]), "r"(a[1]), "r"(a[2]), "r"(a[3]), "r"(b[0]), "r"(b[1]));
}
__device__ __forceinline__ void ldmx4(uint32_t* r, uint32_t addr) {
    asm volatile("ldmatrix.sync.aligned.m8n8.x4.shared.b16 {%0,%1,%2,%3}, [%4];"
        : "=r"(r[0]), "=r"(r[1]), "=r"(r[2]), "=r"(r[3]) : "r"(addr));
}

__device__ __forceinline__ void split4h(float4 f, uint2& hi, uint2& lo) {
    __half h0 = __float2half_rn(f.x), h1 = __float2half_rn(f.y),
           h2 = __float2half_rn(f.z), h3 = __float2half_rn(f.w);
    __half l0 = __float2half_rn(f.x - __half2float(h0)),
           l1 = __float2half_rn(f.y - __half2float(h1)),
           l2 = __float2half_rn(f.z - __half2float(h2)),
           l3 = __float2half_rn(f.w - __half2float(h3));
    __half2 ha = __halves2half2(h0, h1), hb = __halves2half2(h2, h3);
    __half2 la = __halves2half2(l0, l1), lb = __halves2half2(l2, l3);
    hi = make_uint2(*(uint32_t*)&ha, *(uint32_t*)&hb);
    lo = make_uint2(*(uint32_t*)&la, *(uint32_t*)&lb);
}

// ====== GEMM1: 128x128 tile, 8 warps x (64x32) — t = relu(agg@W1 + b1) ======
__global__ __launch_bounds__(256) void gemm_fp16x3_kernel(
        const float* __restrict__ A,
        const __half* __restrict__ Wh,
        const __half* __restrict__ Wl,
        const float* __restrict__ bias, float* __restrict__ C,
        int M, int N, int K, int Kpad, int doRelu) {
    __shared__ __align__(16) uint32_t Ah[128 * WSTRIDE];
    __shared__ __align__(16) uint32_t Al[128 * WSTRIDE];
    __shared__ __align__(16) uint32_t Bh[128 * WSTRIDE];
    __shared__ __align__(16) uint32_t Bl[128 * WSTRIDE];

    const int tid  = threadIdx.x;
    const int lane = tid & 31;
    const int warp = tid >> 5;
    const int g = lane >> 2;
    const int t = lane & 3;
    const int wm = (warp & 1) * 64;
    const int wn = (warp >> 1) * 32;
    const int row0 = blockIdx.y * 128;
    const int col0 = blockIdx.x * 128;

    const uint32_t sAh = smem_u32(Ah), sAl = smem_u32(Al);
    const uint32_t sBh = smem_u32(Bh), sBl = smem_u32(Bl);

    const int l8  = lane & 7;
    const int sel = lane >> 3;
    const int a_row  = l8 + ((sel & 1) << 3);
    const int a_koff = ((sel >> 1) << 3) * 2;
    const int b_row  = l8 + ((sel >> 1) << 3);
    const int b_koff = ((sel & 1) << 3) * 2;

    float c[4][4][4] = {};
    float4 ra[4];
    uint4  rb[4];

    const int nk = (K + KT - 1) / KT;

    #pragma unroll
    for (int it = 0; it < 4; ++it) {
        int idx = tid + it * 256;
        {
            int r = idx >> 3, kq = idx & 7;
            int gr = row0 + r, gk = kq * 4;
            ra[it] = (gr < M && gk < K) ? *(const float4*)(A + (size_t)gr * K + gk)
                                        : make_float4(0.f, 0.f, 0.f, 0.f);
        }
        {
            int term = idx >> 9, rem = idx & 511;
            int r = rem >> 2, q = rem & 3;
            rb[it] = *(const uint4*)((term ? Wl : Wh) + (size_t)(col0 + r) * Kpad + q * 8);
        }
    }

    for (int kt = 0; kt < nk; ++kt) {
        #pragma unroll
        for (int it = 0; it < 4; ++it) {
            int idx = tid + it * 256;
            {
                int r = idx >> 3, kq = idx & 7;
                uint2 hi, lo;
                split4h(ra[it], hi, lo);
                *(uint2*)&Ah[r * WSTRIDE + kq * 2] = hi;
                *(uint2*)&Al[r * WSTRIDE + kq * 2] = lo;
            }
            {
                int term = idx >> 9, rem = idx & 511;
                int r = rem >> 2, q = rem & 3;
                uint32_t* dst = term ? Bl : Bh;
                *(uint4*)&dst[r * WSTRIDE + q * 4] = rb[it];
            }
        }
        __syncthreads();

        if (kt + 1 < nk) {
            int k0 = (kt + 1) * KT;
            #pragma unroll
            for (int it = 0; it < 4; ++it) {
                int idx = tid + it * 256;
                {
                    int r = idx >> 3, kq = idx & 7;
                    int gr = row0 + r, gk = k0 + kq * 4;
                    ra[it] = (gr < M && gk < K) ? *(const float4*)(A + (size_t)gr * K + gk)
                                                : make_float4(0.f, 0.f, 0.f, 0.f);
                }
                {
                    int term = idx >> 9, rem = idx & 511;
                    int r = rem >> 2, q = rem & 3;
                    rb[it] = *(const uint4*)((term ? Wl : Wh) +
                             (size_t)(col0 + r) * Kpad + k0 + q * 8);
                }
            }
        }

        #pragma unroll
        for (int ks = 0; ks < 2; ++ks) {
            const int ka = ks * 32 + a_koff;
            const int kb = ks * 32 + b_koff;
            uint32_t afh[4][4], afl[4][4], bfh[4][2], bfl[4][2];
            #pragma unroll
            for (int i = 0; i < 4; ++i) {
                uint32_t ro = (uint32_t)(wm + i * 16 + a_row) * 80 + ka;
                ldmx4(afh[i], sAh + ro);
                ldmx4(afl[i], sAl + ro);
            }
            #pragma unroll
            for (int j2 = 0; j2 < 2; ++j2) {
                uint32_t ro = (uint32_t)(wn + j2 * 16 + b_row) * 80 + kb;
                uint32_t r[4];
                ldmx4(r, sBh + ro);
                bfh[2 * j2][0] = r[0]; bfh[2 * j2][1] = r[1];
                bfh[2 * j2 + 1][0] = r[2]; bfh[2 * j2 + 1][1] = r[3];
                ldmx4(r, sBl + ro);
                bfl[2 * j2][0] = r[0]; bfl[2 * j2][1] = r[1];
                bfl[2 * j2 + 1][0] = r[2]; bfl[2 * j2 + 1][1] = r[3];
            }
            #pragma unroll
            for (int i = 0; i < 4; ++i)
                #pragma unroll
                for (int j = 0; j < 4; ++j) {
                    mma16f(c[i][j], afl[i], bfh[j]);
                    mma16f(c[i][j], afh[i], bfl[j]);
                    mma16f(c[i][j], afh[i], bfh[j]);
                }
        }
        __syncthreads();
    }

    #pragma unroll
    for (int i = 0; i < 4; ++i) {
        int r = row0 + wm + i * 16 + g;
        #pragma unroll
        for (int j = 0; j < 4; ++j) {
            int cc = col0 + wn + j * 8 + 2 * t;
            if (cc >= N) continue;
            float bx = bias[cc], by = bias[cc + 1];
            if (r < M) {
                float2 v = make_float2(c[i][j][0] + bx, c[i][j][1] + by);
                if (doRelu) { v.x = fmaxf(v.x, 0.f); v.y = fmaxf(v.y, 0.f); }
                *(float2*)&C[(size_t)r * N + cc] = v;
            }
            int r2 = r + 8;
            if (r2 < M) {
                float2 v = make_float2(c[i][j][2] + bx, c[i][j][3] + by);
                if (doRelu) { v.x = fmaxf(v.x, 0.f); v.y = fmaxf(v.y, 0.f); }
                *(float2*)&C[(size_t)r2 * N + cc] = v;
            }
        }
    }
}

// ====== GEMM2: 128x64 tile, 8 warps x (32x32), fused BN stats, no bias ======
__global__ __launch_bounds__(256) void gemm2_n64_kernel(
        const float* __restrict__ A,
        const __half* __restrict__ Wh,
        const __half* __restrict__ Wl,
        float* __restrict__ C,
        int M, int N, int K, int Kpad) {
    __shared__ __align__(16) uint32_t Ah[128 * WSTRIDE];
    __shared__ __align__(16) uint32_t Al[128 * WSTRIDE];
    __shared__ __align__(16) uint32_t Bh[64 * WSTRIDE];
    __shared__ __align__(16) uint32_t Bl[64 * WSTRIDE];

    const int tid  = threadIdx.x;
    const int lane = tid & 31;
    const int warp = tid >> 5;
    const int g = lane >> 2;
    const int t = lane & 3;
    const int wm = (warp & 3) * 32;     // 4 M positions
    const int wn = (warp >> 2) * 32;    // 2 N positions
    const int row0 = blockIdx.y * 128;
    const int col0 = blockIdx.x * 64;

    const uint32_t sAh = smem_u32(Ah), sAl = smem_u32(Al);
    const uint32_t sBh = smem_u32(Bh), sBl = smem_u32(Bl);

    const int l8  = lane & 7;
    const int sel = lane >> 3;
    const int a_row  = l8 + ((sel & 1) << 3);
    const int a_koff = ((sel >> 1) << 3) * 2;
    const int b_row  = l8 + ((sel >> 1) << 3);
    const int b_koff = ((sel & 1) << 3) * 2;

    float c[2][4][4] = {};
    float4 ra[4];
    uint4  rb[2];

    const int nk = (K + KT - 1) / KT;

    #pragma unroll
    for (int it = 0; it < 4; ++it) {
        int idx = tid + it * 256;
        int r = idx >> 3, kq = idx & 7;
        int gr = row0 + r, gk = kq * 4;
        ra[it] = (gr < M && gk < K) ? *(const float4*)(A + (size_t)gr * K + gk)
                                    : make_float4(0.f, 0.f, 0.f, 0.f);
    }
    #pragma unroll
    for (int it = 0; it < 2; ++it) {
        int idx = tid + it * 256;       // 512 uint4 = 2 terms x 64 rows x 4
        int term = idx >> 8, rem = idx & 255;
        int r = rem >> 2, q = rem & 3;
        rb[it] = *(const uint4*)((term ? Wl : Wh) + (size_t)(col0 + r) * Kpad + q * 8);
    }

    for (int kt = 0; kt < nk; ++kt) {
        #pragma unroll
        for (int it = 0; it < 4; ++it) {
            int idx = tid + it * 256;
            int r = idx >> 3, kq = idx & 7;
            uint2 hi, lo;
            split4h(ra[it], hi, lo);
            *(uint2*)&Ah[r * WSTRIDE + kq * 2] = hi;
            *(uint2*)&Al[r * WSTRIDE + kq * 2] = lo;
        }
        #pragma unroll
        for (int it = 0; it < 2; ++it) {
            int idx = tid + it * 256;
            int term = idx >> 8, rem = idx & 255;
            int r = rem >> 2, q = rem & 3;
            uint32_t* dst = term ? Bl : Bh;
            *(uint4*)&dst[r * WSTRIDE + q * 4] = rb[it];
        }
        __syncthreads();

        if (kt + 1 < nk) {
            int k0 = (kt + 1) * KT;
            #pragma unroll
            for (int it = 0; it < 4; ++it) {
                int idx = tid + it * 256;
                int r = idx >> 3, kq = idx & 7;
                int gr = row0 + r, gk = k0 + kq * 4;
                ra[it] = (gr < M && gk < K) ? *(const float4*)(A + (size_t)gr * K + gk)
                                            : make_float4(0.f, 0.f, 0.f, 0.f);
            }
            #pragma unroll
            for (int it = 0; it < 2; ++it) {
                int idx = tid + it * 256;
                int term = idx >> 8, rem = idx & 255;
                int r = rem >> 2, q = rem & 3;
                rb[it] = *(const uint4*)((term ? Wl : Wh) +
                         (size_t)(col0 + r) * Kpad + k0 + q * 8);
            }
        }

        #pragma unroll
        for (int ks = 0; ks < 2; ++ks) {
            const int ka = ks * 32 + a_koff;
            const int kb = ks * 32 + b_koff;
            uint32_t afh[2][4], afl[2][4], bfh[4][2], bfl[4][2];
            #pragma unroll
            for (int i = 0; i < 2; ++i) {
                uint32_t ro = (uint32_t)(wm + i * 16 + a_row) * 80 + ka;
                ldmx4(afh[i], sAh + ro);
                ldmx4(afl[i], sAl + ro);
            }
            #pragma unroll
            for (int j2 = 0; j2 < 2; ++j2) {
                uint32_t ro = (uint32_t)(wn + j2 * 16 + b_row) * 80 + kb;
                uint32_t r[4];
                ldmx4(r, sBh + ro);
                bfh[2 * j2][0] = r[0]; bfh[2 * j2][1] = r[1];
                bfh[2 * j2 + 1][0] = r[2]; bfh[2 * j2 + 1][1] = r[3];
                ldmx4(r, sBl + ro);
                bfl[2 * j2][0] = r[0]; bfl[2 * j2][1] = r[1];
                bfl[2 * j2 + 1][0] = r[2]; bfl[2 * j2 + 1][1] = r[3];
            }
            #pragma unroll
            for (int i = 0; i < 2; ++i)
                #pragma unroll
                for (int j = 0; j < 4; ++j) {
                    mma16f(c[i][j], afl[i], bfh[j]);
                    mma16f(c[i][j], afh[i], bfl[j]);
                    mma16f(c[i][j], afh[i], bfh[j]);
                }
        }
        __syncthreads();
    }

    // ---- fused BN stats (no bias; rows >= M contribute exact zeros) ----
    #pragma unroll
    for (int j = 0; j < 4; ++j) {
        float s0 = 0.f, q0 = 0.f, s1 = 0.f, q1 = 0.f;
        #pragma unroll
        for (int i = 0; i < 2; ++i) {
            float v0 = c[i][j][0], v1 = c[i][j][1];
            float v2 = c[i][j][2], v3 = c[i][j][3];
            s0 += v0 + v2; q0 += v0 * v0 + v2 * v2;
            s1 += v1 + v3; q1 += v1 * v1 + v3 * v3;
        }
        #pragma unroll
        for (int m = 4; m < 32; m <<= 1) {
            s0 += __shfl_xor_sync(0xFFFFFFFFu, s0, m);
            q0 += __shfl_xor_sync(0xFFFFFFFFu, q0, m);
            s1 += __shfl_xor_sync(0xFFFFFFFFu, s1, m);
            q1 += __shfl_xor_sync(0xFFFFFFFFu, q1, m);
        }
        if (lane < 4) {
            int cc = col0 + wn + j * 8 + 2 * t;
            if (cc < EMB) {
                atomicAdd(&g_stats[cc], s0);
                atomicAdd(&g_stats[EMB + cc], q0);
            }
            if (cc + 1 < EMB) {
                atomicAdd(&g_stats[cc + 1], s1);
                atomicAdd(&g_stats[EMB + cc + 1], q1);
            }
        }
    }
    // store y (no bias)
    #pragma unroll
    for (int i = 0; i < 2; ++i) {
        int r = row0 + wm + i * 16 + g;
        #pragma unroll
        for (int j = 0; j < 4; ++j) {
            int cc = col0 + wn + j * 8 + 2 * t;
            if (cc >= N) continue;
            if (r < M)
                *(float2*)&C[(size_t)r * N + cc] = make_float2(c[i][j][0], c[i][j][1]);
            int r2 = r + 8;
            if (r2 < M)
                *(float2*)&C[(size_t)r2 * N + cc] = make_float2(c[i][j][2], c[i][j][3]);
        }
    }
}

// ---------------- BN apply (uncentered stats); fused agg init / pooling ----------------
__global__ void bn_apply_kernel(const float* __restrict__ X,
                                const float* __restrict__ gamma,
                                const float* __restrict__ beta,
                                const int* __restrict__ batch,
                                float* __restrict__ out,
                                int l, int doRelu, int doAgg, int doPool) {
    int idx = blockIdx.x * blockDim.x + threadIdx.x;
    if (idx >= N_NODES * EMB) return;
    int c = idx % EMB;
    float mu  = g_stats[c] * (1.f / N_NODES);
    float var = fmaxf(g_stats[EMB + c] * (1.f / N_NODES) - mu * mu, 0.f);
    float sc = rsqrtf(var + BN_EPS) * gamma[l * EMB + c];
    float v = (X[idx] - mu) * sc + beta[l * EMB + c];
    if (doRelu) v = fmaxf(v, 0.f);
    if (doPool) {
        int i = idx / EMB;
        atomicAdd(&out[(size_t)batch[i] * EMB + c], v);
    } else {
        g_h[idx] = v;
        if (doAgg) g_agg[idx] = v + g_tab[c];
    }
}

// ---------------- pooling ----------------
__global__ void pool_zero_kernel(float* __restrict__ out) {
    int idx = blockIdx.x * blockDim.x + threadIdx.x;
    if (idx < NUM_GRAPHS) g_counts[idx] = 0.f;
    if (idx < NUM_GRAPHS * EMB) out[idx] = 0.f;
}
__global__ void pool_count_kernel(const int* __restrict__ batch) {
    int i = blockIdx.x * blockDim.x + threadIdx.x;
    if (i >= N_NODES) return;
    atomicAdd(&g_counts[batch[i]], 1.f);
}
__global__ void pool_div_kernel(float* __restrict__ out) {
    int idx = blockIdx.x * blockDim.x + threadIdx.x;
    if (idx >= NUM_GRAPHS * EMB) return;
    out[idx] /= fmaxf(g_counts[idx / EMB], 1.f);
}

// ---------------- launch ----------------
extern "C" void kernel_launch(void* const* d_in, const int* in_sizes, int n_in,
                              void* d_out, int out_size) {
    const int*   x        = (const int*)d_in[0];
    const int*   edge_idx = (const int*)d_in[1];
    const int*   edge_att = (const int*)d_in[2];
    const int*   batch    = (const int*)d_in[3];
    const float* x_emb1   = (const float*)d_in[4];
    const float* x_emb2   = (const float*)d_in[5];
    const float* edge_e1  = (const float*)d_in[6];
    const float* edge_e2  = (const float*)d_in[7];
    const float* W1       = (const float*)d_in[8];
    const float* b1       = (const float*)d_in[9];
    const float* W2       = (const float*)d_in[10];
    const float* b2       = (const float*)d_in[11];
    const float* gamma    = (const float*)d_in[12];
    const float* beta     = (const float*)d_in[13];
    float* out = (float*)d_out;
    (void)b2;  // b2 cancels inside BatchNorm

    const int NE = N_NODES * EMB;
    const int TPB = 256;

    init_h_kernel<<<(NE + TPB - 1) / TPB, TPB>>>(x, x_emb1, x_emb2);

    float *p_agg, *p_t;
    __half *p_wh, *p_wl;
    cudaGetSymbolAddress((void**)&p_agg, g_agg);
    cudaGetSymbolAddress((void**)&p_t, g_t);
    cudaGetSymbolAddress((void**)&p_wh, g_wth);
    cudaGetSymbolAddress((void**)&p_wl, g_wtl);

    const int MT = (N_NODES + 127) / 128;   // 782
    dim3 tb(32, 8);
    dim3 tr1(640 / 32, 320 / 32);   // GEMM1 weights: Npad=640, Kpad=320
    dim3 tr2(384 / 32, 640 / 32);   // GEMM2 weights: Npad=384, Kpad=640
    dim3 gg1(5, MT);                // GEMM1: 5 x 128-wide col tiles
    dim3 gg2(5, MT);                // GEMM2: 5 x 64-wide col tiles (320 >= 300)

    // layer-0 aggregation init
    build_tab_kernel<<<(9 * EMB + TPB - 1) / TPB, TPB>>>(edge_e1, edge_e2, 0);
    init_agg_kernel<<<(NE + TPB - 1) / TPB, TPB>>>();

    for (int l = 0; l < NUM_LAYER; ++l) {
        zero_stats_kernel<<<3, 256>>>();   // BEFORE gemm2 accumulates stats
        scatter_edges_kernel<<<(N_EDGES + 7) / 8, 256>>>(edge_idx, edge_att);

        // t = relu(agg @ W1[l] + b1[l])   [N, 600]
        transpose_split_kernel<<<tr1, tb>>>(W1 + (size_t)l * EMB * EMB2,
                                            EMB2, EMB, 640, 320);
        gemm_fp16x3_kernel<<<gg1, 256>>>(p_agg, p_wh, p_wl,
                                         b1 + l * EMB2, p_t,
                                         N_NODES, EMB2, EMB, 320, 1);
        // y = t @ W2[l]   [N, 300]  (bias cancels in BN; stats fused)
        transpose_split_kernel<<<tr2, tb>>>(W2 + (size_t)l * EMB2 * EMB,
                                            EMB, EMB2, 384, 640);
        gemm2_n64_kernel<<<gg2, 256>>>(p_t, p_wh, p_wl, p_agg,
                                       N_NODES, EMB, EMB2, 640);

        int last = (l == NUM_LAYER - 1);
        if (!last) {
            // build next layer's table (no stats touch) BEFORE fused apply+agg
            build_tab_kernel<<<(9 * EMB + TPB - 1) / TPB, TPB>>>(edge_e1, edge_e2, l + 1);
            bn_apply_kernel<<<(NE + TPB - 1) / TPB, TPB>>>(p_agg, gamma, beta,
                                                           batch, out, l, 1, 1, 0);
        } else {
            pool_zero_kernel<<<(NUM_GRAPHS * EMB + TPB - 1) / TPB, TPB>>>(out);
            pool_count_kernel<<<(N_NODES + TPB - 1) / TPB, TPB>>>(batch);
            bn_apply_kernel<<<(NE + TPB - 1) / TPB, TPB>>>(p_agg, gamma, beta,
                                                           batch, out, l, 0, 0, 1);
            pool_div_kernel<<<(NUM_GRAPHS * EMB + TPB - 1) / TPB, TPB>>>(out);
        }
    }
}

// round 13
// speedup vs baseline: 1.1530x; 1.0057x over previous
#include <cuda_runtime.h>
#include <cuda_fp16.h>
#include <math.h>
#include <stdint.h>

#define N_NODES   100000
#define N_EDGES   200000
#define EMB       300
#define EMB2      600
#define NUM_LAYER 5
#define NUM_GRAPHS 5000
#define BN_EPS    1e-5f

// ---------------- device scratch (allocation-free) ----------------
__device__ __align__(16) float g_h[N_NODES * EMB];
__device__ __align__(16) float g_agg[N_NODES * EMB];
__device__ __align__(16) float g_t[N_NODES * EMB2];
__device__ __align__(16) float g_tab[9 * EMB];
__device__ float g_stats[2 * EMB];     // [0:EMB) sum(y), [EMB:2EMB) sum(y^2)
__device__ float g_counts[NUM_GRAPHS];
// transposed + split weights (fp16 hi/lo), zero-padded: max 640x320 / 384x640
__device__ __align__(16) __half g_wth[245760];
__device__ __align__(16) __half g_wtl[245760];

__device__ __forceinline__ uint32_t smem_u32(const void* p) {
    uint32_t a;
    asm("{ .reg .u64 t; cvta.to.shared.u64 t, %1; cvt.u32.u64 %0, t; }" : "=r"(a) : "l"(p));
    return a;
}

// ---------------- h0 = x_emb1[x0] + x_emb2[x1] ----------------
__global__ void init_h_kernel(const int* __restrict__ x,
                              const float* __restrict__ e1,
                              const float* __restrict__ e2) {
    int idx = blockIdx.x * blockDim.x + threadIdx.x;
    if (idx >= N_NODES * EMB) return;
    int i = idx / EMB, c = idx - i * EMB;
    int a = x[2 * i], b = x[2 * i + 1];
    g_h[idx] = e1[a * EMB + c] + e2[b * EMB + c];
}

// ---------------- per-layer eemb table (does NOT touch g_stats) ----------------
__global__ void build_tab_kernel(const float* __restrict__ e1,
                                 const float* __restrict__ e2, int l) {
    int idx = blockIdx.x * blockDim.x + threadIdx.x;
    if (idx >= 9 * EMB) return;
    int t = idx / EMB, c = idx - t * EMB;
    int a = t / 3, b = t - a * 3;
    g_tab[idx] = e1[(l * 6 + a) * EMB + c] + e2[(l * 3 + b) * EMB + c];
}

// zero stats, launched at the top of each layer (before gemm2 accumulates)
__global__ void zero_stats_kernel() {
    int idx = blockIdx.x * blockDim.x + threadIdx.x;
    if (idx < 2 * EMB) g_stats[idx] = 0.f;
}

// ---------------- agg = h + tab[0]  (first layer only) ----------------
__global__ void init_agg_kernel() {
    int idx = blockIdx.x * blockDim.x + threadIdx.x;
    if (idx >= N_NODES * EMB) return;
    g_agg[idx] = g_h[idx] + g_tab[idx % EMB];
}

// ---------------- edge scatter: agg[dst] += h[src] + tab[attr] ----------------
__global__ __launch_bounds__(256) void scatter_edges_kernel(
        const int* __restrict__ ei, const int* __restrict__ ea) {
    int e = blockIdx.x * 8 + (threadIdx.x >> 5);
    if (e >= N_EDGES) return;
    int lane = threadIdx.x & 31;
    int src = ei[e];
    int dst = ei[N_EDGES + e];
    int t = ea[2 * e] * 3 + ea[2 * e + 1];
    const float4* hs = (const float4*)(g_h + (size_t)src * EMB);
    const float4* tb = (const float4*)(g_tab + t * EMB);
    float* ag = g_agg + (size_t)dst * EMB;
    #pragma unroll
    for (int i = lane; i < EMB / 4; i += 32) {
        float4 hv = hs[i];
        float4 tv = tb[i];
        atomicAdd(&ag[4 * i + 0], hv.x + tv.x);
        atomicAdd(&ag[4 * i + 1], hv.y + tv.y);
        atomicAdd(&ag[4 * i + 2], hv.z + tv.z);
        atomicAdd(&ag[4 * i + 3], hv.w + tv.w);
    }
}

// ---------------- weight transpose + fp16 hi/lo split ----------------
__global__ void transpose_split_kernel(const float* __restrict__ W,
                                       int N, int K, int Npad, int Kpad) {
    __shared__ float tile[32][33];
    int tx = threadIdx.x, ty = threadIdx.y;
    int nb = blockIdx.x * 32, kb = blockIdx.y * 32;
    #pragma unroll
    for (int j = 0; j < 4; ++j) {
        int gk = kb + ty + j * 8, gn = nb + tx;
        tile[ty + j * 8][tx] = (gk < K && gn < N) ? W[(size_t)gk * N + gn] : 0.f;
    }
    __syncthreads();
    #pragma unroll
    for (int j = 0; j < 4; ++j) {
        int gn = nb + ty + j * 8, gk = kb + tx;
        if (gn < Npad && gk < Kpad) {
            float v = tile[tx][ty + j * 8];
            __half hi = __float2half_rn(v);
            __half lo = __float2half_rn(v - __half2float(hi));
            g_wth[(size_t)gn * Kpad + gk] = hi;
            g_wtl[(size_t)gn * Kpad + gk] = lo;
        }
    }
}

// ====== unified 3-term split-fp16 GEMM: 128x64 CTA tile, 8 warps x (32x32) ======
// doStats: skip bias, accumulate per-column sum/sumsq into g_stats (GEMM2 path).
// else:    bias + optional relu epilogue (GEMM1 path).
#define KT 32
#define WSTRIDE 20   // words per smem row (16 data + 4 pad) = 80 B

__device__ __forceinline__ void mma16f(float* c, const uint32_t* a, const uint32_t* b) {
    asm volatile(
        "mma.sync.aligned.m16n8k16.row.col.f32.f16.f16.f32 "
        "{%0,%1,%2,%3},{%4,%5,%6,%7},{%8,%9},{%0,%1,%2,%3};\n"
        : "+f"(c[0]), "+f"(c[1]), "+f"(c[2]), "+f"(c[3])
        : "r"(a[0]), "r"(a[1]), "r"(a[2]), "r"(a[3]), "r"(b[0]), "r"(b[1]));
}
__device__ __forceinline__ void ldmx4(uint32_t* r, uint32_t addr) {
    asm volatile("ldmatrix.sync.aligned.m8n8.x4.shared.b16 {%0,%1,%2,%3}, [%4];"
        : "=r"(r[0]), "=r"(r[1]), "=r"(r[2]), "=r"(r[3]) : "r"(addr));
}

__device__ __forceinline__ void split4h(float4 f, uint2& hi, uint2& lo) {
    __half h0 = __float2half_rn(f.x), h1 = __float2half_rn(f.y),
           h2 = __float2half_rn(f.z), h3 = __float2half_rn(f.w);
    __half l0 = __float2half_rn(f.x - __half2float(h0)),
           l1 = __float2half_rn(f.y - __half2float(h1)),
           l2 = __float2half_rn(f.z - __half2float(h2)),
           l3 = __float2half_rn(f.w - __half2float(h3));
    __half2 ha = __halves2half2(h0, h1), hb = __halves2half2(h2, h3);
    __half2 la = __halves2half2(l0, l1), lb = __halves2half2(l2, l3);
    hi = make_uint2(*(uint32_t*)&ha, *(uint32_t*)&hb);
    lo = make_uint2(*(uint32_t*)&la, *(uint32_t*)&lb);
}

__global__ __launch_bounds__(256) void gemm_n64_kernel(
        const float* __restrict__ A,
        const __half* __restrict__ Wh,
        const __half* __restrict__ Wl,
        const float* __restrict__ bias, float* __restrict__ C,
        int M, int N, int K, int Kpad, int doRelu, int doStats) {
    __shared__ __align__(16) uint32_t Ah[128 * WSTRIDE];
    __shared__ __align__(16) uint32_t Al[128 * WSTRIDE];
    __shared__ __align__(16) uint32_t Bh[64 * WSTRIDE];
    __shared__ __align__(16) uint32_t Bl[64 * WSTRIDE];

    const int tid  = threadIdx.x;
    const int lane = tid & 31;
    const int warp = tid >> 5;
    const int g = lane >> 2;
    const int t = lane & 3;
    const int wm = (warp & 3) * 32;     // 4 M positions
    const int wn = (warp >> 2) * 32;    // 2 N positions
    const int row0 = blockIdx.y * 128;
    const int col0 = blockIdx.x * 64;

    const uint32_t sAh = smem_u32(Ah), sAl = smem_u32(Al);
    const uint32_t sBh = smem_u32(Bh), sBl = smem_u32(Bl);

    const int l8  = lane & 7;
    const int sel = lane >> 3;
    const int a_row  = l8 + ((sel & 1) << 3);
    const int a_koff = ((sel >> 1) << 3) * 2;
    const int b_row  = l8 + ((sel >> 1) << 3);
    const int b_koff = ((sel & 1) << 3) * 2;

    float c[2][4][4] = {};
    float4 ra[4];
    uint4  rb[2];

    const int nk = (K + KT - 1) / KT;

    #pragma unroll
    for (int it = 0; it < 4; ++it) {
        int idx = tid + it * 256;
        int r = idx >> 3, kq = idx & 7;
        int gr = row0 + r, gk = kq * 4;
        ra[it] = (gr < M && gk < K) ? *(const float4*)(A + (size_t)gr * K + gk)
                                    : make_float4(0.f, 0.f, 0.f, 0.f);
    }
    #pragma unroll
    for (int it = 0; it < 2; ++it) {
        int idx = tid + it * 256;       // 512 uint4 = 2 terms x 64 rows x 4
        int term = idx >> 8, rem = idx & 255;
        int r = rem >> 2, q = rem & 3;
        rb[it] = *(const uint4*)((term ? Wl : Wh) + (size_t)(col0 + r) * Kpad + q * 8);
    }

    for (int kt = 0; kt < nk; ++kt) {
        #pragma unroll
        for (int it = 0; it < 4; ++it) {
            int idx = tid + it * 256;
            int r = idx >> 3, kq = idx & 7;
            uint2 hi, lo;
            split4h(ra[it], hi, lo);
            *(uint2*)&Ah[r * WSTRIDE + kq * 2] = hi;
            *(uint2*)&Al[r * WSTRIDE + kq * 2] = lo;
        }
        #pragma unroll
        for (int it = 0; it < 2; ++it) {
            int idx = tid + it * 256;
            int term = idx >> 8, rem = idx & 255;
            int r = rem >> 2, q = rem & 3;
            uint32_t* dst = term ? Bl : Bh;
            *(uint4*)&dst[r * WSTRIDE + q * 4] = rb[it];
        }
        __syncthreads();

        if (kt + 1 < nk) {
            int k0 = (kt + 1) * KT;
            #pragma unroll
            for (int it = 0; it < 4; ++it) {
                int idx = tid + it * 256;
                int r = idx >> 3, kq = idx & 7;
                int gr = row0 + r, gk = k0 + kq * 4;
                ra[it] = (gr < M && gk < K) ? *(const float4*)(A + (size_t)gr * K + gk)
                                            : make_float4(0.f, 0.f, 0.f, 0.f);
            }
            #pragma unroll
            for (int it = 0; it < 2; ++it) {
                int idx = tid + it * 256;
                int term = idx >> 8, rem = idx & 255;
                int r = rem >> 2, q = rem & 3;
                rb[it] = *(const uint4*)((term ? Wl : Wh) +
                         (size_t)(col0 + r) * Kpad + k0 + q * 8);
            }
        }

        #pragma unroll
        for (int ks = 0; ks < 2; ++ks) {
            const int ka = ks * 32 + a_koff;
            const int kb = ks * 32 + b_koff;
            uint32_t afh[2][4], afl[2][4], bfh[4][2], bfl[4][2];
            #pragma unroll
            for (int i = 0; i < 2; ++i) {
                uint32_t ro = (uint32_t)(wm + i * 16 + a_row) * 80 + ka;
                ldmx4(afh[i], sAh + ro);
                ldmx4(afl[i], sAl + ro);
            }
            #pragma unroll
            for (int j2 = 0; j2 < 2; ++j2) {
                uint32_t ro = (uint32_t)(wn + j2 * 16 + b_row) * 80 + kb;
                uint32_t r[4];
                ldmx4(r, sBh + ro);
                bfh[2 * j2][0] = r[0]; bfh[2 * j2][1] = r[1];
                bfh[2 * j2 + 1][0] = r[2]; bfh[2 * j2 + 1][1] = r[3];
                ldmx4(r, sBl + ro);
                bfl[2 * j2][0] = r[0]; bfl[2 * j2][1] = r[1];
                bfl[2 * j2 + 1][0] = r[2]; bfl[2 * j2 + 1][1] = r[3];
            }
            #pragma unroll
            for (int i = 0; i < 2; ++i)
                #pragma unroll
                for (int j = 0; j < 4; ++j) {
                    mma16f(c[i][j], afl[i], bfh[j]);
                    mma16f(c[i][j], afh[i], bfl[j]);
                    mma16f(c[i][j], afh[i], bfh[j]);
                }
        }
        __syncthreads();
    }

    if (doStats) {
        // ---- fused BN stats (no bias; rows >= M contribute exact zeros) ----
        #pragma unroll
        for (int j = 0; j < 4; ++j) {
            float s0 = 0.f, q0 = 0.f, s1 = 0.f, q1 = 0.f;
            #pragma unroll
            for (int i = 0; i < 2; ++i) {
                float v0 = c[i][j][0], v1 = c[i][j][1];
                float v2 = c[i][j][2], v3 = c[i][j][3];
                s0 += v0 + v2; q0 += v0 * v0 + v2 * v2;
                s1 += v1 + v3; q1 += v1 * v1 + v3 * v3;
            }
            #pragma unroll
            for (int m = 4; m < 32; m <<= 1) {
                s0 += __shfl_xor_sync(0xFFFFFFFFu, s0, m);
                q0 += __shfl_xor_sync(0xFFFFFFFFu, q0, m);
                s1 += __shfl_xor_sync(0xFFFFFFFFu, s1, m);
                q1 += __shfl_xor_sync(0xFFFFFFFFu, q1, m);
            }
            if (lane < 4) {
                int cc = col0 + wn + j * 8 + 2 * t;
                if (cc < EMB) {
                    atomicAdd(&g_stats[cc], s0);
                    atomicAdd(&g_stats[EMB + cc], q0);
                }
                if (cc + 1 < EMB) {
                    atomicAdd(&g_stats[cc + 1], s1);
                    atomicAdd(&g_stats[EMB + cc + 1], q1);
                }
            }
        }
        // store y (no bias)
        #pragma unroll
        for (int i = 0; i < 2; ++i) {
            int r = row0 + wm + i * 16 + g;
            #pragma unroll
            for (int j = 0; j < 4; ++j) {
                int cc = col0 + wn + j * 8 + 2 * t;
                if (cc >= N) continue;
                if (r < M)
                    *(float2*)&C[(size_t)r * N + cc] = make_float2(c[i][j][0], c[i][j][1]);
                int r2 = r + 8;
                if (r2 < M)
                    *(float2*)&C[(size_t)r2 * N + cc] = make_float2(c[i][j][2], c[i][j][3]);
            }
        }
    } else {
        // ---- bias + optional relu ----
        #pragma unroll
        for (int i = 0; i < 2; ++i) {
            int r = row0 + wm + i * 16 + g;
            #pragma unroll
            for (int j = 0; j < 4; ++j) {
                int cc = col0 + wn + j * 8 + 2 * t;
                if (cc >= N) continue;
                float bx = bias[cc], by = bias[cc + 1];
                if (r < M) {
                    float2 v = make_float2(c[i][j][0] + bx, c[i][j][1] + by);
                    if (doRelu) { v.x = fmaxf(v.x, 0.f); v.y = fmaxf(v.y, 0.f); }
                    *(float2*)&C[(size_t)r * N + cc] = v;
                }
                int r2 = r + 8;
                if (r2 < M) {
                    float2 v = make_float2(c[i][j][2] + bx, c[i][j][3] + by);
                    if (doRelu) { v.x = fmaxf(v.x, 0.f); v.y = fmaxf(v.y, 0.f); }
                    *(float2*)&C[(size_t)r2 * N + cc] = v;
                }
            }
        }
    }
}

// ---------------- BN apply (uncentered stats); fused agg init / pooling ----------------
__global__ void bn_apply_kernel(const float* __restrict__ X,
                                const float* __restrict__ gamma,
                                const float* __restrict__ beta,
                                const int* __restrict__ batch,
                                float* __restrict__ out,
                                int l, int doRelu, int doAgg, int doPool) {
    int idx = blockIdx.x * blockDim.x + threadIdx.x;
    if (idx >= N_NODES * EMB) return;
    int c = idx % EMB;
    float mu  = g_stats[c] * (1.f / N_NODES);
    float var = fmaxf(g_stats[EMB + c] * (1.f / N_NODES) - mu * mu, 0.f);
    float sc = rsqrtf(var + BN_EPS) * gamma[l * EMB + c];
    float v = (X[idx] - mu) * sc + beta[l * EMB + c];
    if (doRelu) v = fmaxf(v, 0.f);
    if (doPool) {
        int i = idx / EMB;
        atomicAdd(&out[(size_t)batch[i] * EMB + c], v);
    } else {
        g_h[idx] = v;
        if (doAgg) g_agg[idx] = v + g_tab[c];
    }
}

// ---------------- pooling ----------------
__global__ void pool_zero_kernel(float* __restrict__ out) {
    int idx = blockIdx.x * blockDim.x + threadIdx.x;
    if (idx < NUM_GRAPHS) g_counts[idx] = 0.f;
    if (idx < NUM_GRAPHS * EMB) out[idx] = 0.f;
}
__global__ void pool_count_kernel(const int* __restrict__ batch) {
    int i = blockIdx.x * blockDim.x + threadIdx.x;
    if (i >= N_NODES) return;
    atomicAdd(&g_counts[batch[i]], 1.f);
}
__global__ void pool_div_kernel(float* __restrict__ out) {
    int idx = blockIdx.x * blockDim.x + threadIdx.x;
    if (idx >= NUM_GRAPHS * EMB) return;
    out[idx] /= fmaxf(g_counts[idx / EMB], 1.f);
}

// ---------------- launch ----------------
extern "C" void kernel_launch(void* const* d_in, const int* in_sizes, int n_in,
                              void* d_out, int out_size) {
    const int*   x        = (const int*)d_in[0];
    const int*   edge_idx = (const int*)d_in[1];
    const int*   edge_att = (const int*)d_in[2];
    const int*   batch    = (const int*)d_in[3];
    const float* x_emb1   = (const float*)d_in[4];
    const float* x_emb2   = (const float*)d_in[5];
    const float* edge_e1  = (const float*)d_in[6];
    const float* edge_e2  = (const float*)d_in[7];
    const float* W1       = (const float*)d_in[8];
    const float* b1       = (const float*)d_in[9];
    const float* W2       = (const float*)d_in[10];
    const float* b2       = (const float*)d_in[11];
    const float* gamma    = (const float*)d_in[12];
    const float* beta     = (const float*)d_in[13];
    float* out = (float*)d_out;
    (void)b2;  // b2 cancels inside BatchNorm

    const int NE = N_NODES * EMB;
    const int TPB = 256;

    init_h_kernel<<<(NE + TPB - 1) / TPB, TPB>>>(x, x_emb1, x_emb2);

    float *p_agg, *p_t;
    __half *p_wh, *p_wl;
    cudaGetSymbolAddress((void**)&p_agg, g_agg);
    cudaGetSymbolAddress((void**)&p_t, g_t);
    cudaGetSymbolAddress((void**)&p_wh, g_wth);
    cudaGetSymbolAddress((void**)&p_wl, g_wtl);

    const int MT = (N_NODES + 127) / 128;   // 782
    dim3 tb(32, 8);
    dim3 tr1(640 / 32, 320 / 32);   // GEMM1 weights: Npad=640, Kpad=320
    dim3 tr2(384 / 32, 640 / 32);   // GEMM2 weights: Npad=384, Kpad=640
    dim3 gg1(10, MT);               // GEMM1: 10 x 64-wide col tiles (640 >= 600)
    dim3 gg2(5, MT);                // GEMM2:  5 x 64-wide col tiles (320 >= 300)

    // layer-0 aggregation init
    build_tab_kernel<<<(9 * EMB + TPB - 1) / TPB, TPB>>>(edge_e1, edge_e2, 0);
    init_agg_kernel<<<(NE + TPB - 1) / TPB, TPB>>>();

    for (int l = 0; l < NUM_LAYER; ++l) {
        zero_stats_kernel<<<3, 256>>>();   // BEFORE gemm2 accumulates stats
        scatter_edges_kernel<<<(N_EDGES + 7) / 8, 256>>>(edge_idx, edge_att);

        // t = relu(agg @ W1[l] + b1[l])   [N, 600]
        transpose_split_kernel<<<tr1, tb>>>(W1 + (size_t)l * EMB * EMB2,
                                            EMB2, EMB, 640, 320);
        gemm_n64_kernel<<<gg1, 256>>>(p_agg, p_wh, p_wl,
                                      b1 + l * EMB2, p_t,
                                      N_NODES, EMB2, EMB, 320, 1, 0);
        // y = t @ W2[l]   [N, 300]  (bias cancels in BN; stats fused)
        transpose_split_kernel<<<tr2, tb>>>(W2 + (size_t)l * EMB2 * EMB,
                                            EMB, EMB2, 384, 640);
        gemm_n64_kernel<<<gg2, 256>>>(p_t, p_wh, p_wl,
                                      b2, p_agg,
                                      N_NODES, EMB, EMB2, 640, 0, 1);

        int last = (l == NUM_LAYER - 1);
        if (!last) {
            // build next layer's table (no stats touch) BEFORE fused apply+agg
            build_tab_kernel<<<(9 * EMB + TPB - 1) / TPB, TPB>>>(edge_e1, edge_e2, l + 1);
            bn_apply_kernel<<<(NE + TPB - 1) / TPB, TPB>>>(p_agg, gamma, beta,
                                                           batch, out, l, 1, 1, 0);
        } else {
            pool_zero_kernel<<<(NUM_GRAPHS * EMB + TPB - 1) / TPB, TPB>>>(out);
            pool_count_kernel<<<(N_NODES + TPB - 1) / TPB, TPB>>>(batch);
            bn_apply_kernel<<<(NE + TPB - 1) / TPB, TPB>>>(p_agg, gamma, beta,
                                                           batch, out, l, 0, 0, 1);
            pool_div_kernel<<<(NUM_GRAPHS * EMB + TPB - 1) / TPB, TPB>>>(out);
        }
    }
}

// round 14
// speedup vs baseline: 1.1931x; 1.0348x over previous
#include <cuda_runtime.h>
#include <cuda_fp16.h>
#include <math.h>
#include <stdint.h>

#define N_NODES   100000
#define N_EDGES   200000
#define EMB       300
#define EMB2      600
#define NUM_LAYER 5
#define NUM_GRAPHS 5000
#define BN_EPS    1e-5f

// ---------------- device scratch (allocation-free) ----------------
__device__ __align__(16) float g_h[N_NODES * EMB];
__device__ __align__(16) float g_agg[N_NODES * EMB];
__device__ __align__(16) float g_t[N_NODES * EMB2];
__device__ __align__(16) float g_tab[9 * EMB];
__device__ float g_stats[2 * EMB];     // [0:EMB) sum(y), [EMB:2EMB) sum(y^2)
__device__ float g_counts[NUM_GRAPHS];
// transposed + split weights (fp16 hi/lo), zero-padded: max 640x320 / 384x640
__device__ __align__(16) __half g_wth[245760];
__device__ __align__(16) __half g_wtl[245760];

__device__ __forceinline__ uint32_t smem_u32(const void* p) {
    uint32_t a;
    asm("{ .reg .u64 t; cvta.to.shared.u64 t, %1; cvt.u32.u64 %0, t; }" : "=r"(a) : "l"(p));
    return a;
}

// ---------------- h0 = x_emb1[x0] + x_emb2[x1] ----------------
__global__ void init_h_kernel(const int* __restrict__ x,
                              const float* __restrict__ e1,
                              const float* __restrict__ e2) {
    int idx = blockIdx.x * blockDim.x + threadIdx.x;
    if (idx >= N_NODES * EMB) return;
    int i = idx / EMB, c = idx - i * EMB;
    int a = x[2 * i], b = x[2 * i + 1];
    g_h[idx] = e1[a * EMB + c] + e2[b * EMB + c];
}

// ---------------- per-layer eemb table (does NOT touch g_stats) ----------------
__global__ void build_tab_kernel(const float* __restrict__ e1,
                                 const float* __restrict__ e2, int l) {
    int idx = blockIdx.x * blockDim.x + threadIdx.x;
    if (idx >= 9 * EMB) return;
    int t = idx / EMB, c = idx - t * EMB;
    int a = t / 3, b = t - a * 3;
    g_tab[idx] = e1[(l * 6 + a) * EMB + c] + e2[(l * 3 + b) * EMB + c];
}

// zero stats, launched at the top of each layer (before gemm2 accumulates)
__global__ void zero_stats_kernel() {
    int idx = blockIdx.x * blockDim.x + threadIdx.x;
    if (idx < 2 * EMB) g_stats[idx] = 0.f;
}

// ---------------- agg = h + tab[0]  (first layer only) ----------------
__global__ void init_agg_kernel() {
    int idx = blockIdx.x * blockDim.x + threadIdx.x;
    if (idx >= N_NODES * EMB) return;
    g_agg[idx] = g_h[idx] + g_tab[idx % EMB];
}

// ---------------- edge scatter: agg[dst] += h[src] + tab[attr] ----------------
__global__ __launch_bounds__(256) void scatter_edges_kernel(
        const int* __restrict__ ei, const int* __restrict__ ea) {
    int e = blockIdx.x * 8 + (threadIdx.x >> 5);
    if (e >= N_EDGES) return;
    int lane = threadIdx.x & 31;
    int src = ei[e];
    int dst = ei[N_EDGES + e];
    int t = ea[2 * e] * 3 + ea[2 * e + 1];
    const float4* hs = (const float4*)(g_h + (size_t)src * EMB);
    const float4* tb = (const float4*)(g_tab + t * EMB);
    float* ag = g_agg + (size_t)dst * EMB;
    #pragma unroll
    for (int i = lane; i < EMB / 4; i += 32) {
        float4 hv = hs[i];
        float4 tv = tb[i];
        atomicAdd(&ag[4 * i + 0], hv.x + tv.x);
        atomicAdd(&ag[4 * i + 1], hv.y + tv.y);
        atomicAdd(&ag[4 * i + 2], hv.z + tv.z);
        atomicAdd(&ag[4 * i + 3], hv.w + tv.w);
    }
}

// ---------------- weight transpose + fp16 hi/lo split ----------------
__global__ void transpose_split_kernel(const float* __restrict__ W,
                                       int N, int K, int Npad, int Kpad) {
    __shared__ float tile[32][33];
    int tx = threadIdx.x, ty = threadIdx.y;
    int nb = blockIdx.x * 32, kb = blockIdx.y * 32;
    #pragma unroll
    for (int j = 0; j < 4; ++j) {
        int gk = kb + ty + j * 8, gn = nb + tx;
        tile[ty + j * 8][tx] = (gk < K && gn < N) ? W[(size_t)gk * N + gn] : 0.f;
    }
    __syncthreads();
    #pragma unroll
    for (int j = 0; j < 4; ++j) {
        int gn = nb + ty + j * 8, gk = kb + tx;
        if (gn < Npad && gk < Kpad) {
            float v = tile[tx][ty + j * 8];
            __half hi = __float2half_rn(v);
            __half lo = __float2half_rn(v - __half2float(hi));
            g_wth[(size_t)gn * Kpad + gk] = hi;
            g_wtl[(size_t)gn * Kpad + gk] = lo;
        }
    }
}

// ====== unified 3-term split-fp16 GEMM: 128x64 CTA tile, double-buffered ======
#define KT 32
#define WSTRIDE 20                     // words per smem row (16 data + 4 pad)
#define AH_OFF  0
#define AL_OFF  (128 * WSTRIDE)        // 2560
#define BH_OFF  (256 * WSTRIDE)        // 5120
#define BL_OFF  (320 * WSTRIDE)        // 6400
#define STAGEW  (384 * WSTRIDE)        // 7680 words = 30720 B per stage
#define GEMM_SMEM (2 * STAGEW * 4)     // 61440 B

__device__ __forceinline__ void mma16f(float* c, const uint32_t* a, const uint32_t* b) {
    asm volatile(
        "mma.sync.aligned.m16n8k16.row.col.f32.f16.f16.f32 "
        "{%0,%1,%2,%3},{%4,%5,%6,%7},{%8,%9},{%0,%1,%2,%3};\n"
        : "+f"(c[0]), "+f"(c[1]), "+f"(c[2]), "+f"(c[3])
        : "r"(a[0]), "r"(a[1]), "r"(a[2]), "r"(a[3]), "r"(b[0]), "r"(b[1]));
}
__device__ __forceinline__ void ldmx4(uint32_t* r, uint32_t addr) {
    asm volatile("ldmatrix.sync.aligned.m8n8.x4.shared.b16 {%0,%1,%2,%3}, [%4];"
        : "=r"(r[0]), "=r"(r[1]), "=r"(r[2]), "=r"(r[3]) : "r"(addr));
}

__device__ __forceinline__ void split4h(float4 f, uint2& hi, uint2& lo) {
    __half h0 = __float2half_rn(f.x), h1 = __float2half_rn(f.y),
           h2 = __float2half_rn(f.z), h3 = __float2half_rn(f.w);
    __half l0 = __float2half_rn(f.x - __half2float(h0)),
           l1 = __float2half_rn(f.y - __half2float(h1)),
           l2 = __float2half_rn(f.z - __half2float(h2)),
           l3 = __float2half_rn(f.w - __half2float(h3));
    __half2 ha = __halves2half2(h0, h1), hb = __halves2half2(h2, h3);
    __half2 la = __halves2half2(l0, l1), lb = __halves2half2(l2, l3);
    hi = make_uint2(*(uint32_t*)&ha, *(uint32_t*)&hb);
    lo = make_uint2(*(uint32_t*)&la, *(uint32_t*)&lb);
}

__global__ __launch_bounds__(256, 2) void gemm_n64_kernel(
        const float* __restrict__ A,
        const __half* __restrict__ Wh,
        const __half* __restrict__ Wl,
        const float* __restrict__ bias, float* __restrict__ C,
        int M, int N, int K, int Kpad, int doRelu, int doStats) {
    extern __shared__ __align__(16) uint32_t sm[];

    const int tid  = threadIdx.x;
    const int lane = tid & 31;
    const int warp = tid >> 5;
    const int g = lane >> 2;
    const int t = lane & 3;
    const int wm = (warp & 3) * 32;     // 4 M positions
    const int wn = (warp >> 2) * 32;    // 2 N positions
    const int row0 = blockIdx.y * 128;
    const int col0 = blockIdx.x * 64;

    const uint32_t sb0 = smem_u32(sm);

    const int l8  = lane & 7;
    const int sel = lane >> 3;
    const int a_row  = l8 + ((sel & 1) << 3);
    const int a_koff = ((sel >> 1) << 3) * 2;
    const int b_row  = l8 + ((sel >> 1) << 3);
    const int b_koff = ((sel & 1) << 3) * 2;

    float c[2][4][4] = {};
    float4 ra[4];
    uint4  rb[2];

    const int nk = (K + KT - 1) / KT;

    // ---- prefetch tile 0 + store into stage 0 ----
    #pragma unroll
    for (int it = 0; it < 4; ++it) {
        int idx = tid + it * 256;
        int r = idx >> 3, kq = idx & 7;
        int gr = row0 + r, gk = kq * 4;
        ra[it] = (gr < M && gk < K) ? *(const float4*)(A + (size_t)gr * K + gk)
                                    : make_float4(0.f, 0.f, 0.f, 0.f);
    }
    #pragma unroll
    for (int it = 0; it < 2; ++it) {
        int idx = tid + it * 256;
        int term = idx >> 8, rem = idx & 255;
        int r = rem >> 2, q = rem & 3;
        rb[it] = *(const uint4*)((term ? Wl : Wh) + (size_t)(col0 + r) * Kpad + q * 8);
    }
    {
        uint32_t* S = sm;
        #pragma unroll
        for (int it = 0; it < 4; ++it) {
            int idx = tid + it * 256;
            int r = idx >> 3, kq = idx & 7;
            uint2 hi, lo;
            split4h(ra[it], hi, lo);
            *(uint2*)&S[AH_OFF + r * WSTRIDE + kq * 2] = hi;
            *(uint2*)&S[AL_OFF + r * WSTRIDE + kq * 2] = lo;
        }
        #pragma unroll
        for (int it = 0; it < 2; ++it) {
            int idx = tid + it * 256;
            int term = idx >> 8, rem = idx & 255;
            int r = rem >> 2, q = rem & 3;
            *(uint4*)&S[(term ? BL_OFF : BH_OFF) + r * WSTRIDE + q * 4] = rb[it];
        }
    }
    __syncthreads();

    for (int kt = 0; kt < nk; ++kt) {
        const uint32_t sb = sb0 + (kt & 1) * (STAGEW * 4);

        // ---- prefetch tile kt+1 into registers ----
        if (kt + 1 < nk) {
            int k0 = (kt + 1) * KT;
            #pragma unroll
            for (int it = 0; it < 4; ++it) {
                int idx = tid + it * 256;
                int r = idx >> 3, kq = idx & 7;
                int gr = row0 + r, gk = k0 + kq * 4;
                ra[it] = (gr < M && gk < K) ? *(const float4*)(A + (size_t)gr * K + gk)
                                            : make_float4(0.f, 0.f, 0.f, 0.f);
            }
            #pragma unroll
            for (int it = 0; it < 2; ++it) {
                int idx = tid + it * 256;
                int term = idx >> 8, rem = idx & 255;
                int r = rem >> 2, q = rem & 3;
                rb[it] = *(const uint4*)((term ? Wl : Wh) +
                         (size_t)(col0 + r) * Kpad + k0 + q * 8);
            }
        }

        // ---- compute tile kt from stage kt&1 ----
        const uint32_t sAh = sb + AH_OFF * 4;
        const uint32_t sAl = sb + AL_OFF * 4;
        const uint32_t sBh = sb + BH_OFF * 4;
        const uint32_t sBl = sb + BL_OFF * 4;
        #pragma unroll
        for (int ks = 0; ks < 2; ++ks) {
            const int ka = ks * 32 + a_koff;
            const int kb = ks * 32 + b_koff;
            uint32_t afh[2][4], afl[2][4], bfh[4][2], bfl[4][2];
            #pragma unroll
            for (int i = 0; i < 2; ++i) {
                uint32_t ro = (uint32_t)(wm + i * 16 + a_row) * 80 + ka;
                ldmx4(afh[i], sAh + ro);
                ldmx4(afl[i], sAl + ro);
            }
            #pragma unroll
            for (int j2 = 0; j2 < 2; ++j2) {
                uint32_t ro = (uint32_t)(wn + j2 * 16 + b_row) * 80 + kb;
                uint32_t r[4];
                ldmx4(r, sBh + ro);
                bfh[2 * j2][0] = r[0]; bfh[2 * j2][1] = r[1];
                bfh[2 * j2 + 1][0] = r[2]; bfh[2 * j2 + 1][1] = r[3];
                ldmx4(r, sBl + ro);
                bfl[2 * j2][0] = r[0]; bfl[2 * j2][1] = r[1];
                bfl[2 * j2 + 1][0] = r[2]; bfl[2 * j2 + 1][1] = r[3];
            }
            #pragma unroll
            for (int i = 0; i < 2; ++i)
                #pragma unroll
                for (int j = 0; j < 4; ++j) {
                    mma16f(c[i][j], afl[i], bfh[j]);
                    mma16f(c[i][j], afh[i], bfl[j]);
                    mma16f(c[i][j], afh[i], bfh[j]);
                }
        }

        // ---- store tile kt+1 into the other stage (WAR-safe: 2 apart) ----
        if (kt + 1 < nk) {
            uint32_t* S = sm + ((kt + 1) & 1) * STAGEW;
            #pragma unroll
            for (int it = 0; it < 4; ++it) {
                int idx = tid + it * 256;
                int r = idx >> 3, kq = idx & 7;
                uint2 hi, lo;
                split4h(ra[it], hi, lo);
                *(uint2*)&S[AH_OFF + r * WSTRIDE + kq * 2] = hi;
                *(uint2*)&S[AL_OFF + r * WSTRIDE + kq * 2] = lo;
            }
            #pragma unroll
            for (int it = 0; it < 2; ++it) {
                int idx = tid + it * 256;
                int term = idx >> 8, rem = idx & 255;
                int r = rem >> 2, q = rem & 3;
                *(uint4*)&S[(term ? BL_OFF : BH_OFF) + r * WSTRIDE + q * 4] = rb[it];
            }
        }
        __syncthreads();   // single barrier per k-tile
    }

    if (doStats) {
        // ---- fused BN stats (no bias; rows >= M contribute exact zeros) ----
        #pragma unroll
        for (int j = 0; j < 4; ++j) {
            float s0 = 0.f, q0 = 0.f, s1 = 0.f, q1 = 0.f;
            #pragma unroll
            for (int i = 0; i < 2; ++i) {
                float v0 = c[i][j][0], v1 = c[i][j][1];
                float v2 = c[i][j][2], v3 = c[i][j][3];
                s0 += v0 + v2; q0 += v0 * v0 + v2 * v2;
                s1 += v1 + v3; q1 += v1 * v1 + v3 * v3;
            }
            #pragma unroll
            for (int m = 4; m < 32; m <<= 1) {
                s0 += __shfl_xor_sync(0xFFFFFFFFu, s0, m);
                q0 += __shfl_xor_sync(0xFFFFFFFFu, q0, m);
                s1 += __shfl_xor_sync(0xFFFFFFFFu, s1, m);
                q1 += __shfl_xor_sync(0xFFFFFFFFu, q1, m);
            }
            if (lane < 4) {
                int cc = col0 + wn + j * 8 + 2 * t;
                if (cc < EMB) {
                    atomicAdd(&g_stats[cc], s0);
                    atomicAdd(&g_stats[EMB + cc], q0);
                }
                if (cc + 1 < EMB) {
                    atomicAdd(&g_stats[cc + 1], s1);
                    atomicAdd(&g_stats[EMB + cc + 1], q1);
                }
            }
        }
        #pragma unroll
        for (int i = 0; i < 2; ++i) {
            int r = row0 + wm + i * 16 + g;
            #pragma unroll
            for (int j = 0; j < 4; ++j) {
                int cc = col0 + wn + j * 8 + 2 * t;
                if (cc >= N) continue;
                if (r < M)
                    *(float2*)&C[(size_t)r * N + cc] = make_float2(c[i][j][0], c[i][j][1]);
                int r2 = r + 8;
                if (r2 < M)
                    *(float2*)&C[(size_t)r2 * N + cc] = make_float2(c[i][j][2], c[i][j][3]);
            }
        }
    } else {
        #pragma unroll
        for (int i = 0; i < 2; ++i) {
            int r = row0 + wm + i * 16 + g;
            #pragma unroll
            for (int j = 0; j < 4; ++j) {
                int cc = col0 + wn + j * 8 + 2 * t;
                if (cc >= N) continue;
                float bx = bias[cc], by = bias[cc + 1];
                if (r < M) {
                    float2 v = make_float2(c[i][j][0] + bx, c[i][j][1] + by);
                    if (doRelu) { v.x = fmaxf(v.x, 0.f); v.y = fmaxf(v.y, 0.f); }
                    *(float2*)&C[(size_t)r * N + cc] = v;
                }
                int r2 = r + 8;
                if (r2 < M) {
                    float2 v = make_float2(c[i][j][2] + bx, c[i][j][3] + by);
                    if (doRelu) { v.x = fmaxf(v.x, 0.f); v.y = fmaxf(v.y, 0.f); }
                    *(float2*)&C[(size_t)r2 * N + cc] = v;
                }
            }
        }
    }
}

// ---------------- BN apply (uncentered stats); fused agg init / pooling ----------------
__global__ void bn_apply_kernel(const float* __restrict__ X,
                                const float* __restrict__ gamma,
                                const float* __restrict__ beta,
                                const int* __restrict__ batch,
                                float* __restrict__ out,
                                int l, int doRelu, int doAgg, int doPool) {
    int idx = blockIdx.x * blockDim.x + threadIdx.x;
    if (idx >= N_NODES * EMB) return;
    int c = idx % EMB;
    float mu  = g_stats[c] * (1.f / N_NODES);
    float var = fmaxf(g_stats[EMB + c] * (1.f / N_NODES) - mu * mu, 0.f);
    float sc = rsqrtf(var + BN_EPS) * gamma[l * EMB + c];
    float v = (X[idx] - mu) * sc + beta[l * EMB + c];
    if (doRelu) v = fmaxf(v, 0.f);
    if (doPool) {
        int i = idx / EMB;
        atomicAdd(&out[(size_t)batch[i] * EMB + c], v);
    } else {
        g_h[idx] = v;
        if (doAgg) g_agg[idx] = v + g_tab[c];
    }
}

// ---------------- pooling ----------------
__global__ void pool_zero_kernel(float* __restrict__ out) {
    int idx = blockIdx.x * blockDim.x + threadIdx.x;
    if (idx < NUM_GRAPHS) g_counts[idx] = 0.f;
    if (idx < NUM_GRAPHS * EMB) out[idx] = 0.f;
}
__global__ void pool_count_kernel(const int* __restrict__ batch) {
    int i = blockIdx.x * blockDim.x + threadIdx.x;
    if (i >= N_NODES) return;
    atomicAdd(&g_counts[batch[i]], 1.f);
}
__global__ void pool_div_kernel(float* __restrict__ out) {
    int idx = blockIdx.x * blockDim.x + threadIdx.x;
    if (idx >= NUM_GRAPHS * EMB) return;
    out[idx] /= fmaxf(g_counts[idx / EMB], 1.f);
}

// ---------------- launch ----------------
extern "C" void kernel_launch(void* const* d_in, const int* in_sizes, int n_in,
                              void* d_out, int out_size) {
    const int*   x        = (const int*)d_in[0];
    const int*   edge_idx = (const int*)d_in[1];
    const int*   edge_att = (const int*)d_in[2];
    const int*   batch    = (const int*)d_in[3];
    const float* x_emb1   = (const float*)d_in[4];
    const float* x_emb2   = (const float*)d_in[5];
    const float* edge_e1  = (const float*)d_in[6];
    const float* edge_e2  = (const float*)d_in[7];
    const float* W1       = (const float*)d_in[8];
    const float* b1       = (const float*)d_in[9];
    const float* W2       = (const float*)d_in[10];
    const float* b2       = (const float*)d_in[11];
    const float* gamma    = (const float*)d_in[12];
    const float* beta     = (const float*)d_in[13];
    float* out = (float*)d_out;
    (void)b2;  // b2 cancels inside BatchNorm

    const int NE = N_NODES * EMB;
    const int TPB = 256;

    cudaFuncSetAttribute(gemm_n64_kernel,
                         cudaFuncAttributeMaxDynamicSharedMemorySize, GEMM_SMEM);

    init_h_kernel<<<(NE + TPB - 1) / TPB, TPB>>>(x, x_emb1, x_emb2);

    float *p_agg, *p_t;
    __half *p_wh, *p_wl;
    cudaGetSymbolAddress((void**)&p_agg, g_agg);
    cudaGetSymbolAddress((void**)&p_t, g_t);
    cudaGetSymbolAddress((void**)&p_wh, g_wth);
    cudaGetSymbolAddress((void**)&p_wl, g_wtl);

    const int MT = (N_NODES + 127) / 128;   // 782
    dim3 tb(32, 8);
    dim3 tr1(640 / 32, 320 / 32);   // GEMM1 weights: Npad=640, Kpad=320
    dim3 tr2(384 / 32, 640 / 32);   // GEMM2 weights: Npad=384, Kpad=640
    dim3 gg1(10, MT);               // GEMM1: 10 x 64-wide col tiles
    dim3 gg2(5, MT);                // GEMM2:  5 x 64-wide col tiles

    // layer-0 aggregation init
    build_tab_kernel<<<(9 * EMB + TPB - 1) / TPB, TPB>>>(edge_e1, edge_e2, 0);
    init_agg_kernel<<<(NE + TPB - 1) / TPB, TPB>>>();

    for (int l = 0; l < NUM_LAYER; ++l) {
        zero_stats_kernel<<<3, 256>>>();   // BEFORE gemm2 accumulates stats
        scatter_edges_kernel<<<(N_EDGES + 7) / 8, 256>>>(edge_idx, edge_att);

        // t = relu(agg @ W1[l] + b1[l])   [N, 600]
        transpose_split_kernel<<<tr1, tb>>>(W1 + (size_t)l * EMB * EMB2,
                                            EMB2, EMB, 640, 320);
        gemm_n64_kernel<<<gg1, 256, GEMM_SMEM>>>(p_agg, p_wh, p_wl,
                                                 b1 + l * EMB2, p_t,
                                                 N_NODES, EMB2, EMB, 320, 1, 0);
        // y = t @ W2[l]   [N, 300]  (bias cancels in BN; stats fused)
        transpose_split_kernel<<<tr2, tb>>>(W2 + (size_t)l * EMB2 * EMB,
                                            EMB, EMB2, 384, 640);
        gemm_n64_kernel<<<gg2, 256, GEMM_SMEM>>>(p_t, p_wh, p_wl,
                                                 b2, p_agg,
                                                 N_NODES, EMB, EMB2, 640, 0, 1);

        int last = (l == NUM_LAYER - 1);
        if (!last) {
            // build next layer's table (no stats touch) BEFORE fused apply+agg
            build_tab_kernel<<<(9 * EMB + TPB - 1) / TPB, TPB>>>(edge_e1, edge_e2, l + 1);
            bn_apply_kernel<<<(NE + TPB - 1) / TPB, TPB>>>(p_agg, gamma, beta,
                                                           batch, out, l, 1, 1, 0);
        } else {
            pool_zero_kernel<<<(NUM_GRAPHS * EMB + TPB - 1) / TPB, TPB>>>(out);
            pool_count_kernel<<<(N_NODES + TPB - 1) / TPB, TPB>>>(batch);
            bn_apply_kernel<<<(NE + TPB - 1) / TPB, TPB>>>(p_agg, gamma, beta,
                                                           batch, out, l, 0, 0, 1);
            pool_div_kernel<<<(NUM_GRAPHS * EMB + TPB - 1) / TPB, TPB>>>(out);
        }
    }
}

// round 15
// speedup vs baseline: 1.3185x; 1.1051x over previous
#include <cuda_runtime.h>
#include <cuda_fp16.h>
#include <math.h>
#include <stdint.h>

#define N_NODES   100000
#define N_EDGES   200000
#define EMB       300
#define EMB2      600
#define NUM_LAYER 5
#define NUM_GRAPHS 5000
#define BN_EPS    1e-5f

// ---------------- device scratch (allocation-free) ----------------
__device__ __align__(16) float g_h[N_NODES * EMB];
__device__ __align__(16) float g_agg[N_NODES * EMB];
__device__ __align__(16) float g_t[N_NODES * EMB2];
__device__ __align__(16) float g_tab[9 * EMB];
__device__ float g_stats[2 * EMB];     // [0:EMB) sum(y), [EMB:2EMB) sum(y^2)
__device__ float g_counts[NUM_GRAPHS];
// CSR by destination (built once per launch; graph constant across layers)
__device__ int g_rowptr[N_NODES + 1];
__device__ int g_fill[N_NODES];
__device__ int g_bsum[1024];
__device__ uint32_t g_esrc[N_EDGES];   // packed (src << 4) | attr_type
// transposed + split weights (fp16 hi/lo), zero-padded: max 640x320 / 384x640
__device__ __align__(16) __half g_wth[245760];
__device__ __align__(16) __half g_wtl[245760];

__device__ __forceinline__ uint32_t smem_u32(const void* p) {
    uint32_t a;
    asm("{ .reg .u64 t; cvta.to.shared.u64 t, %1; cvt.u32.u64 %0, t; }" : "=r"(a) : "l"(p));
    return a;
}
__device__ __forceinline__ float4 f4add(float4 a, float4 b) {
    return make_float4(a.x + b.x, a.y + b.y, a.z + b.z, a.w + b.w);
}

// ---------------- h0 = x_emb1[x0] + x_emb2[x1] ----------------
__global__ void init_h_kernel(const int* __restrict__ x,
                              const float* __restrict__ e1,
                              const float* __restrict__ e2) {
    int idx = blockIdx.x * blockDim.x + threadIdx.x;
    if (idx >= N_NODES * EMB) return;
    int i = idx / EMB, c = idx - i * EMB;
    int a = x[2 * i], b = x[2 * i + 1];
    g_h[idx] = e1[a * EMB + c] + e2[b * EMB + c];
}

// ---------------- per-layer eemb table ----------------
__global__ void build_tab_kernel(const float* __restrict__ e1,
                                 const float* __restrict__ e2, int l) {
    int idx = blockIdx.x * blockDim.x + threadIdx.x;
    if (idx >= 9 * EMB) return;
    int t = idx / EMB, c = idx - t * EMB;
    int a = t / 3, b = t - a * 3;
    g_tab[idx] = e1[(l * 6 + a) * EMB + c] + e2[(l * 3 + b) * EMB + c];
}

__global__ void zero_stats_kernel() {
    int idx = blockIdx.x * blockDim.x + threadIdx.x;
    if (idx < 2 * EMB) g_stats[idx] = 0.f;
}

// ================= CSR build (once per launch) =================
__global__ void csr_zero_kernel() {
    int i = blockIdx.x * blockDim.x + threadIdx.x;
    if (i <= N_NODES) g_rowptr[i] = 0;
}
__global__ void csr_count_kernel(const int* __restrict__ ei) {
    int e = blockIdx.x * blockDim.x + threadIdx.x;
    if (e >= N_EDGES) return;
    atomicAdd(&g_rowptr[ei[N_EDGES + e] + 1], 1);
}
// inclusive scan, blocks of 1024
__global__ void csr_scan1_kernel(int n) {
    __shared__ int sh[1024];
    int gid = blockIdx.x * 1024 + threadIdx.x;
    int v = (gid < n) ? g_rowptr[gid] : 0;
    sh[threadIdx.x] = v;
    __syncthreads();
    #pragma unroll
    for (int off = 1; off < 1024; off <<= 1) {
        int t = (threadIdx.x >= off) ? sh[threadIdx.x - off] : 0;
        __syncthreads();
        sh[threadIdx.x] += t;
        __syncthreads();
    }
    if (gid < n) g_rowptr[gid] = sh[threadIdx.x];
    if (threadIdx.x == 1023) g_bsum[blockIdx.x] = sh[1023];
}
__global__ void csr_scan2_kernel(int nb) {   // exclusive scan of block sums, 1 block
    __shared__ int sh[1024];
    int v = (threadIdx.x < nb) ? g_bsum[threadIdx.x] : 0;
    sh[threadIdx.x] = v;
    __syncthreads();
    #pragma unroll
    for (int off = 1; off < 1024; off <<= 1) {
        int t = (threadIdx.x >= off) ? sh[threadIdx.x - off] : 0;
        __syncthreads();
        sh[threadIdx.x] += t;
        __syncthreads();
    }
    if (threadIdx.x < nb) g_bsum[threadIdx.x] = sh[threadIdx.x] - v;
}
__global__ void csr_scan3_kernel(int n) {
    int gid = blockIdx.x * 1024 + threadIdx.x;
    if (gid < n) g_rowptr[gid] += g_bsum[blockIdx.x];
}
__global__ void csr_fill_kernel() {
    int i = blockIdx.x * blockDim.x + threadIdx.x;
    if (i < N_NODES) g_fill[i] = g_rowptr[i];
}
__global__ void csr_place_kernel(const int* __restrict__ ei,
                                 const int* __restrict__ ea) {
    int e = blockIdx.x * blockDim.x + threadIdx.x;
    if (e >= N_EDGES) return;
    int d = ei[N_EDGES + e];
    int pos = atomicAdd(&g_fill[d], 1);
    int t = ea[2 * e] * 3 + ea[2 * e + 1];
    g_esrc[pos] = ((uint32_t)ei[e] << 4) | (uint32_t)t;
}

// ---------------- gather: agg[i] = h[i] + tab0 + sum_in (h[src] + tab[t]) ----------------
__global__ __launch_bounds__(256) void gather_kernel() {
    int node = blockIdx.x * 8 + (threadIdx.x >> 5);
    if (node >= N_NODES) return;
    int lane = threadIdx.x & 31;
    int beg = g_rowptr[node], end = g_rowptr[node + 1];

    const float4* hd = (const float4*)(g_h + (size_t)node * EMB);
    const float4* t0 = (const float4*)g_tab;
    const int c0 = lane, c1 = lane + 32, c2 = lane + 64;   // c2 valid iff lane < 11

    float4 a0 = f4add(hd[c0], t0[c0]);
    float4 a1 = f4add(hd[c1], t0[c1]);
    float4 a2 = (lane < 11) ? f4add(hd[c2], t0[c2]) : make_float4(0, 0, 0, 0);

    for (int e = beg; e < end; ++e) {
        uint32_t v = g_esrc[e];
        const float4* hs = (const float4*)(g_h + (size_t)(v >> 4) * EMB);
        const float4* tb = (const float4*)(g_tab + (v & 15u) * EMB);
        a0 = f4add(a0, f4add(hs[c0], tb[c0]));
        a1 = f4add(a1, f4add(hs[c1], tb[c1]));
        if (lane < 11) a2 = f4add(a2, f4add(hs[c2], tb[c2]));
    }
    float4* ag = (float4*)(g_agg + (size_t)node * EMB);
    ag[c0] = a0;
    ag[c1] = a1;
    if (lane < 11) ag[c2] = a2;
}

// ---------------- weight transpose + fp16 hi/lo split ----------------
__global__ void transpose_split_kernel(const float* __restrict__ W,
                                       int N, int K, int Npad, int Kpad) {
    __shared__ float tile[32][33];
    int tx = threadIdx.x, ty = threadIdx.y;
    int nb = blockIdx.x * 32, kb = blockIdx.y * 32;
    #pragma unroll
    for (int j = 0; j < 4; ++j) {
        int gk = kb + ty + j * 8, gn = nb + tx;
        tile[ty + j * 8][tx] = (gk < K && gn < N) ? W[(size_t)gk * N + gn] : 0.f;
    }
    __syncthreads();
    #pragma unroll
    for (int j = 0; j < 4; ++j) {
        int gn = nb + ty + j * 8, gk = kb + tx;
        if (gn < Npad && gk < Kpad) {
            float v = tile[tx][ty + j * 8];
            __half hi = __float2half_rn(v);
            __half lo = __float2half_rn(v - __half2float(hi));
            g_wth[(size_t)gn * Kpad + gk] = hi;
            g_wtl[(size_t)gn * Kpad + gk] = lo;
        }
    }
}

// ====== unified 3-term split-fp16 GEMM: 128x64 CTA tile, double-buffered ======
#define KT 32
#define WSTRIDE 20
#define AH_OFF  0
#define AL_OFF  (128 * WSTRIDE)
#define BH_OFF  (256 * WSTRIDE)
#define BL_OFF  (320 * WSTRIDE)
#define STAGEW  (384 * WSTRIDE)
#define GEMM_SMEM (2 * STAGEW * 4)     // 61440 B

__device__ __forceinline__ void mma16f(float* c, const uint32_t* a, const uint32_t* b) {
    asm volatile(
        "mma.sync.aligned.m16n8k16.row.col.f32.f16.f16.f32 "
        "{%0,%1,%2,%3},{%4,%5,%6,%7},{%8,%9},{%0,%1,%2,%3};\n"
        : "+f"(c[0]), "+f"(c[1]), "+f"(c[2]), "+f"(c[3])
        : "r"(a[0]), "r"(a[1]), "r"(a[2]), "r"(a[3]), "r"(b[0]), "r"(b[1]));
}
__device__ __forceinline__ void ldmx4(uint32_t* r, uint32_t addr) {
    asm volatile("ldmatrix.sync.aligned.m8n8.x4.shared.b16 {%0,%1,%2,%3}, [%4];"
        : "=r"(r[0]), "=r"(r[1]), "=r"(r[2]), "=r"(r[3]) : "r"(addr));
}

__device__ __forceinline__ void split4h(float4 f, uint2& hi, uint2& lo) {
    __half h0 = __float2half_rn(f.x), h1 = __float2half_rn(f.y),
           h2 = __float2half_rn(f.z), h3 = __float2half_rn(f.w);
    __half l0 = __float2half_rn(f.x - __half2float(h0)),
           l1 = __float2half_rn(f.y - __half2float(h1)),
           l2 = __float2half_rn(f.z - __half2float(h2)),
           l3 = __float2half_rn(f.w - __half2float(h3));
    __half2 ha = __halves2half2(h0, h1), hb = __halves2half2(h2, h3);
    __half2 la = __halves2half2(l0, l1), lb = __halves2half2(l2, l3);
    hi = make_uint2(*(uint32_t*)&ha, *(uint32_t*)&hb);
    lo = make_uint2(*(uint32_t*)&la, *(uint32_t*)&lb);
}

__global__ __launch_bounds__(256, 2) void gemm_n64_kernel(
        const float* __restrict__ A,
        const __half* __restrict__ Wh,
        const __half* __restrict__ Wl,
        const float* __restrict__ bias, float* __restrict__ C,
        int M, int N, int K, int Kpad, int doRelu, int doStats) {
    extern __shared__ __align__(16) uint32_t sm[];

    const int tid  = threadIdx.x;
    const int lane = tid & 31;
    const int warp = tid >> 5;
    const int g = lane >> 2;
    const int t = lane & 3;
    const int wm = (warp & 3) * 32;
    const int wn = (warp >> 2) * 32;
    const int row0 = blockIdx.y * 128;
    const int col0 = blockIdx.x * 64;

    const uint32_t sb0 = smem_u32(sm);

    const int l8  = lane & 7;
    const int sel = lane >> 3;
    const int a_row  = l8 + ((sel & 1) << 3);
    const int a_koff = ((sel >> 1) << 3) * 2;
    const int b_row  = l8 + ((sel >> 1) << 3);
    const int b_koff = ((sel & 1) << 3) * 2;

    float c[2][4][4] = {};
    float4 ra[4];
    uint4  rb[2];

    const int nk = (K + KT - 1) / KT;

    #pragma unroll
    for (int it = 0; it < 4; ++it) {
        int idx = tid + it * 256;
        int r = idx >> 3, kq = idx & 7;
        int gr = row0 + r, gk = kq * 4;
        ra[it] = (gr < M && gk < K) ? *(const float4*)(A + (size_t)gr * K + gk)
                                    : make_float4(0.f, 0.f, 0.f, 0.f);
    }
    #pragma unroll
    for (int it = 0; it < 2; ++it) {
        int idx = tid + it * 256;
        int term = idx >> 8, rem = idx & 255;
        int r = rem >> 2, q = rem & 3;
        rb[it] = *(const uint4*)((term ? Wl : Wh) + (size_t)(col0 + r) * Kpad + q * 8);
    }
    {
        uint32_t* S = sm;
        #pragma unroll
        for (int it = 0; it < 4; ++it) {
            int idx = tid + it * 256;
            int r = idx >> 3, kq = idx & 7;
            uint2 hi, lo;
            split4h(ra[it], hi, lo);
            *(uint2*)&S[AH_OFF + r * WSTRIDE + kq * 2] = hi;
            *(uint2*)&S[AL_OFF + r * WSTRIDE + kq * 2] = lo;
        }
        #pragma unroll
        for (int it = 0; it < 2; ++it) {
            int idx = tid + it * 256;
            int term = idx >> 8, rem = idx & 255;
            int r = rem >> 2, q = rem & 3;
            *(uint4*)&S[(term ? BL_OFF : BH_OFF) + r * WSTRIDE + q * 4] = rb[it];
        }
    }
    __syncthreads();

    for (int kt = 0; kt < nk; ++kt) {
        const uint32_t sb = sb0 + (kt & 1) * (STAGEW * 4);

        if (kt + 1 < nk) {
            int k0 = (kt + 1) * KT;
            #pragma unroll
            for (int it = 0; it < 4; ++it) {
                int idx = tid + it * 256;
                int r = idx >> 3, kq = idx & 7;
                int gr = row0 + r, gk = k0 + kq * 4;
                ra[it] = (gr < M && gk < K) ? *(const float4*)(A + (size_t)gr * K + gk)
                                            : make_float4(0.f, 0.f, 0.f, 0.f);
            }
            #pragma unroll
            for (int it = 0; it < 2; ++it) {
                int idx = tid + it * 256;
                int term = idx >> 8, rem = idx & 255;
                int r = rem >> 2, q = rem & 3;
                rb[it] = *(const uint4*)((term ? Wl : Wh) +
                         (size_t)(col0 + r) * Kpad + k0 + q * 8);
            }
        }

        const uint32_t sAh = sb + AH_OFF * 4;
        const uint32_t sAl = sb + AL_OFF * 4;
        const uint32_t sBh = sb + BH_OFF * 4;
        const uint32_t sBl = sb + BL_OFF * 4;
        #pragma unroll
        for (int ks = 0; ks < 2; ++ks) {
            const int ka = ks * 32 + a_koff;
            const int kb = ks * 32 + b_koff;
            uint32_t afh[2][4], afl[2][4], bfh[4][2], bfl[4][2];
            #pragma unroll
            for (int i = 0; i < 2; ++i) {
                uint32_t ro = (uint32_t)(wm + i * 16 + a_row) * 80 + ka;
                ldmx4(afh[i], sAh + ro);
                ldmx4(afl[i], sAl + ro);
            }
            #pragma unroll
            for (int j2 = 0; j2 < 2; ++j2) {
                uint32_t ro = (uint32_t)(wn + j2 * 16 + b_row) * 80 + kb;
                uint32_t r[4];
                ldmx4(r, sBh + ro);
                bfh[2 * j2][0] = r[0]; bfh[2 * j2][1] = r[1];
                bfh[2 * j2 + 1][0] = r[2]; bfh[2 * j2 + 1][1] = r[3];
                ldmx4(r, sBl + ro);
                bfl[2 * j2][0] = r[0]; bfl[2 * j2][1] = r[1];
                bfl[2 * j2 + 1][0] = r[2]; bfl[2 * j2 + 1][1] = r[3];
            }
            #pragma unroll
            for (int i = 0; i < 2; ++i)
                #pragma unroll
                for (int j = 0; j < 4; ++j) {
                    mma16f(c[i][j], afl[i], bfh[j]);
                    mma16f(c[i][j], afh[i], bfl[j]);
                    mma16f(c[i][j], afh[i], bfh[j]);
                }
        }

        if (kt + 1 < nk) {
            uint32_t* S = sm + ((kt + 1) & 1) * STAGEW;
            #pragma unroll
            for (int it = 0; it < 4; ++it) {
                int idx = tid + it * 256;
                int r = idx >> 3, kq = idx & 7;
                uint2 hi, lo;
                split4h(ra[it], hi, lo);
                *(uint2*)&S[AH_OFF + r * WSTRIDE + kq * 2] = hi;
                *(uint2*)&S[AL_OFF + r * WSTRIDE + kq * 2] = lo;
            }
            #pragma unroll
            for (int it = 0; it < 2; ++it) {
                int idx = tid + it * 256;
                int term = idx >> 8, rem = idx & 255;
                int r = rem >> 2, q = rem & 3;
                *(uint4*)&S[(term ? BL_OFF : BH_OFF) + r * WSTRIDE + q * 4] = rb[it];
            }
        }
        __syncthreads();
    }

    if (doStats) {
        #pragma unroll
        for (int j = 0; j < 4; ++j) {
            float s0 = 0.f, q0 = 0.f, s1 = 0.f, q1 = 0.f;
            #pragma unroll
            for (int i = 0; i < 2; ++i) {
                float v0 = c[i][j][0], v1 = c[i][j][1];
                float v2 = c[i][j][2], v3 = c[i][j][3];
                s0 += v0 + v2; q0 += v0 * v0 + v2 * v2;
                s1 += v1 + v3; q1 += v1 * v1 + v3 * v3;
            }
            #pragma unroll
            for (int m = 4; m < 32; m <<= 1) {
                s0 += __shfl_xor_sync(0xFFFFFFFFu, s0, m);
                q0 += __shfl_xor_sync(0xFFFFFFFFu, q0, m);
                s1 += __shfl_xor_sync(0xFFFFFFFFu, s1, m);
                q1 += __shfl_xor_sync(0xFFFFFFFFu, q1, m);
            }
            if (lane < 4) {
                int cc = col0 + wn + j * 8 + 2 * t;
                if (cc < EMB) {
                    atomicAdd(&g_stats[cc], s0);
                    atomicAdd(&g_stats[EMB + cc], q0);
                }
                if (cc + 1 < EMB) {
                    atomicAdd(&g_stats[cc + 1], s1);
                    atomicAdd(&g_stats[EMB + cc + 1], q1);
                }
            }
        }
        #pragma unroll
        for (int i = 0; i < 2; ++i) {
            int r = row0 + wm + i * 16 + g;
            #pragma unroll
            for (int j = 0; j < 4; ++j) {
                int cc = col0 + wn + j * 8 + 2 * t;
                if (cc >= N) continue;
                if (r < M)
                    *(float2*)&C[(size_t)r * N + cc] = make_float2(c[i][j][0], c[i][j][1]);
                int r2 = r + 8;
                if (r2 < M)
                    *(float2*)&C[(size_t)r2 * N + cc] = make_float2(c[i][j][2], c[i][j][3]);
            }
        }
    } else {
        #pragma unroll
        for (int i = 0; i < 2; ++i) {
            int r = row0 + wm + i * 16 + g;
            #pragma unroll
            for (int j = 0; j < 4; ++j) {
                int cc = col0 + wn + j * 8 + 2 * t;
                if (cc >= N) continue;
                float bx = bias[cc], by = bias[cc + 1];
                if (r < M) {
                    float2 v = make_float2(c[i][j][0] + bx, c[i][j][1] + by);
                    if (doRelu) { v.x = fmaxf(v.x, 0.f); v.y = fmaxf(v.y, 0.f); }
                    *(float2*)&C[(size_t)r * N + cc] = v;
                }
                int r2 = r + 8;
                if (r2 < M) {
                    float2 v = make_float2(c[i][j][2] + bx, c[i][j][3] + by);
                    if (doRelu) { v.x = fmaxf(v.x, 0.f); v.y = fmaxf(v.y, 0.f); }
                    *(float2*)&C[(size_t)r2 * N + cc] = v;
                }
            }
        }
    }
}

// ---------------- BN apply (uncentered stats); writes h; optional pooling ----------------
__global__ void bn_apply_kernel(const float* __restrict__ X,
                                const float* __restrict__ gamma,
                                const float* __restrict__ beta,
                                const int* __restrict__ batch,
                                float* __restrict__ out,
                                int l, int doRelu, int doPool) {
    int idx = blockIdx.x * blockDim.x + threadIdx.x;
    if (idx >= N_NODES * EMB) return;
    int c = idx % EMB;
    float mu  = g_stats[c] * (1.f / N_NODES);
    float var = fmaxf(g_stats[EMB + c] * (1.f / N_NODES) - mu * mu, 0.f);
    float sc = rsqrtf(var + BN_EPS) * gamma[l * EMB + c];
    float v = (X[idx] - mu) * sc + beta[l * EMB + c];
    if (doRelu) v = fmaxf(v, 0.f);
    if (doPool) {
        int i = idx / EMB;
        atomicAdd(&out[(size_t)batch[i] * EMB + c], v);
    } else {
        g_h[idx] = v;
    }
}

// ---------------- pooling ----------------
__global__ void pool_zero_kernel(float* __restrict__ out) {
    int idx = blockIdx.x * blockDim.x + threadIdx.x;
    if (idx < NUM_GRAPHS) g_counts[idx] = 0.f;
    if (idx < NUM_GRAPHS * EMB) out[idx] = 0.f;
}
__global__ void pool_count_kernel(const int* __restrict__ batch) {
    int i = blockIdx.x * blockDim.x + threadIdx.x;
    if (i >= N_NODES) return;
    atomicAdd(&g_counts[batch[i]], 1.f);
}
__global__ void pool_div_kernel(float* __restrict__ out) {
    int idx = blockIdx.x * blockDim.x + threadIdx.x;
    if (idx >= NUM_GRAPHS * EMB) return;
    out[idx] /= fmaxf(g_counts[idx / EMB], 1.f);
}

// ---------------- launch ----------------
extern "C" void kernel_launch(void* const* d_in, const int* in_sizes, int n_in,
                              void* d_out, int out_size) {
    const int*   x        = (const int*)d_in[0];
    const int*   edge_idx = (const int*)d_in[1];
    const int*   edge_att = (const int*)d_in[2];
    const int*   batch    = (const int*)d_in[3];
    const float* x_emb1   = (const float*)d_in[4];
    const float* x_emb2   = (const float*)d_in[5];
    const float* edge_e1  = (const float*)d_in[6];
    const float* edge_e2  = (const float*)d_in[7];
    const float* W1       = (const float*)d_in[8];
    const float* b1       = (const float*)d_in[9];
    const float* W2       = (const float*)d_in[10];
    const float* b2       = (const float*)d_in[11];
    const float* gamma    = (const float*)d_in[12];
    const float* beta     = (const float*)d_in[13];
    float* out = (float*)d_out;
    (void)b2;  // b2 cancels inside BatchNorm

    const int NE = N_NODES * EMB;
    const int TPB = 256;

    cudaFuncSetAttribute(gemm_n64_kernel,
                         cudaFuncAttributeMaxDynamicSharedMemorySize, GEMM_SMEM);

    init_h_kernel<<<(NE + TPB - 1) / TPB, TPB>>>(x, x_emb1, x_emb2);

    // ---- build CSR once (graph constant across layers) ----
    const int NS = N_NODES + 1;                 // 100001
    const int SCAN_BLOCKS = (NS + 1023) / 1024; // 98
    csr_zero_kernel<<<(NS + TPB - 1) / TPB, TPB>>>();
    csr_count_kernel<<<(N_EDGES + TPB - 1) / TPB, TPB>>>(edge_idx);
    csr_scan1_kernel<<<SCAN_BLOCKS, 1024>>>(NS);
    csr_scan2_kernel<<<1, 1024>>>(SCAN_BLOCKS);
    csr_scan3_kernel<<<SCAN_BLOCKS, 1024>>>(NS);
    csr_fill_kernel<<<(N_NODES + TPB - 1) / TPB, TPB>>>();
    csr_place_kernel<<<(N_EDGES + TPB - 1) / TPB, TPB>>>(edge_idx, edge_att);

    float *p_agg, *p_t;
    __half *p_wh, *p_wl;
    cudaGetSymbolAddress((void**)&p_agg, g_agg);
    cudaGetSymbolAddress((void**)&p_t, g_t);
    cudaGetSymbolAddress((void**)&p_wh, g_wth);
    cudaGetSymbolAddress((void**)&p_wl, g_wtl);

    const int MT = (N_NODES + 127) / 128;   // 782
    dim3 tb(32, 8);
    dim3 tr1(640 / 32, 320 / 32);   // GEMM1 weights: Npad=640, Kpad=320
    dim3 tr2(384 / 32, 640 / 32);   // GEMM2 weights: Npad=384, Kpad=640
    dim3 gg1(10, MT);
    dim3 gg2(5, MT);

    for (int l = 0; l < NUM_LAYER; ++l) {
        zero_stats_kernel<<<3, 256>>>();
        build_tab_kernel<<<(9 * EMB + TPB - 1) / TPB, TPB>>>(edge_e1, edge_e2, l);
        gather_kernel<<<(N_NODES + 7) / 8, 256>>>();

        // t = relu(agg @ W1[l] + b1[l])   [N, 600]
        transpose_split_kernel<<<tr1, tb>>>(W1 + (size_t)l * EMB * EMB2,
                                            EMB2, EMB, 640, 320);
        gemm_n64_kernel<<<gg1, 256, GEMM_SMEM>>>(p_agg, p_wh, p_wl,
                                                 b1 + l * EMB2, p_t,
                                                 N_NODES, EMB2, EMB, 320, 1, 0);
        // y = t @ W2[l]   [N, 300]  (bias cancels in BN; stats fused)
        transpose_split_kernel<<<tr2, tb>>>(W2 + (size_t)l * EMB2 * EMB,
                                            EMB, EMB2, 384, 640);
        gemm_n64_kernel<<<gg2, 256, GEMM_SMEM>>>(p_t, p_wh, p_wl,
                                                 b2, p_agg,
                                                 N_NODES, EMB, EMB2, 640, 0, 1);

        int last = (l == NUM_LAYER - 1);
        if (!last) {
            bn_apply_kernel<<<(NE + TPB - 1) / TPB, TPB>>>(p_agg, gamma, beta,
                                                           batch, out, l, 1, 0);
        } else {
            pool_zero_kernel<<<(NUM_GRAPHS * EMB + TPB - 1) / TPB, TPB>>>(out);
            pool_count_kernel<<<(N_NODES + TPB - 1) / TPB, TPB>>>(batch);
            bn_apply_kernel<<<(NE + TPB - 1) / TPB, TPB>>>(p_agg, gamma, beta,
                                                           batch, out, l, 0, 1);
            pool_div_kernel<<<(NUM_GRAPHS * EMB + TPB - 1) / TPB, TPB>>>(out);
        }
    }
}

// round 16
// speedup vs baseline: 1.3663x; 1.0363x over previous
#include <cuda_runtime.h>
#include <cuda_fp16.h>
#include <math.h>
#include <stdint.h>

#define N_NODES   100000
#define N_EDGES   200000
#define EMB       300
#define EMB2      600
#define NUM_LAYER 5
#define NUM_GRAPHS 5000
#define BN_EPS    1e-5f

// ---------------- device scratch (allocation-free) ----------------
__device__ __align__(16) float g_h[N_NODES * EMB];
__device__ __align__(16) float g_agg[N_NODES * EMB];
__device__ __align__(16) float g_t[N_NODES * EMB2];
__device__ __align__(16) float g_tab[9 * EMB];
__device__ float g_stats[2 * EMB];            // [0:EMB) sum(y), [EMB:2EMB) sum(y^2)
__device__ __align__(16) float g_bnco[2 * EMB]; // [0:EMB) scale, [EMB:2EMB) offset
__device__ float g_counts[NUM_GRAPHS];
// CSR by destination (built once per launch; graph constant across layers)
__device__ int g_rowptr[N_NODES + 1];
__device__ int g_fill[N_NODES];
__device__ int g_bsum[1024];
__device__ uint32_t g_esrc[N_EDGES];   // packed (src << 4) | attr_type
// transposed + split weights (fp16 hi/lo), zero-padded: max 640x320 / 384x640
__device__ __align__(16) __half g_wth[245760];
__device__ __align__(16) __half g_wtl[245760];

__device__ __forceinline__ uint32_t smem_u32(const void* p) {
    uint32_t a;
    asm("{ .reg .u64 t; cvta.to.shared.u64 t, %1; cvt.u32.u64 %0, t; }" : "=r"(a) : "l"(p));
    return a;
}
__device__ __forceinline__ float4 f4add(float4 a, float4 b) {
    return make_float4(a.x + b.x, a.y + b.y, a.z + b.z, a.w + b.w);
}
__device__ __forceinline__ float4 bnrelu4(float4 y, float4 s, float4 o) {
    return make_float4(fmaxf(fmaf(y.x, s.x, o.x), 0.f),
                       fmaxf(fmaf(y.y, s.y, o.y), 0.f),
                       fmaxf(fmaf(y.z, s.z, o.z), 0.f),
                       fmaxf(fmaf(y.w, s.w, o.w), 0.f));
}

// ---------------- h0 = x_emb1[x0] + x_emb2[x1] ----------------
__global__ void init_h_kernel(const int* __restrict__ x,
                              const float* __restrict__ e1,
                              const float* __restrict__ e2) {
    int idx = blockIdx.x * blockDim.x + threadIdx.x;
    if (idx >= N_NODES * EMB) return;
    int i = idx / EMB, c = idx - i * EMB;
    int a = x[2 * i], b = x[2 * i + 1];
    g_h[idx] = e1[a * EMB + c] + e2[b * EMB + c];
}

// ---------------- per-layer eemb table ----------------
__global__ void build_tab_kernel(const float* __restrict__ e1,
                                 const float* __restrict__ e2, int l) {
    int idx = blockIdx.x * blockDim.x + threadIdx.x;
    if (idx >= 9 * EMB) return;
    int t = idx / EMB, c = idx - t * EMB;
    int a = t / 3, b = t - a * 3;
    g_tab[idx] = e1[(l * 6 + a) * EMB + c] + e2[(l * 3 + b) * EMB + c];
}

__global__ void zero_stats_kernel() {
    int idx = blockIdx.x * blockDim.x + threadIdx.x;
    if (idx < 2 * EMB) g_stats[idx] = 0.f;
}

// BN affine coefficients for layer l (from stats of layer l): h = y*sc + off
__global__ void bnco_kernel(const float* __restrict__ gamma,
                            const float* __restrict__ beta, int l) {
    int c = blockIdx.x * blockDim.x + threadIdx.x;
    if (c >= EMB) return;
    float mu  = g_stats[c] * (1.f / N_NODES);
    float var = fmaxf(g_stats[EMB + c] * (1.f / N_NODES) - mu * mu, 0.f);
    float sc  = rsqrtf(var + BN_EPS) * gamma[l * EMB + c];
    g_bnco[c]       = sc;
    g_bnco[EMB + c] = beta[l * EMB + c] - mu * sc;
}

// ================= CSR build (once per launch) =================
__global__ void csr_zero_kernel() {
    int i = blockIdx.x * blockDim.x + threadIdx.x;
    if (i <= N_NODES) g_rowptr[i] = 0;
}
__global__ void csr_count_kernel(const int* __restrict__ ei) {
    int e = blockIdx.x * blockDim.x + threadIdx.x;
    if (e >= N_EDGES) return;
    atomicAdd(&g_rowptr[ei[N_EDGES + e] + 1], 1);
}
__global__ void csr_scan1_kernel(int n) {
    __shared__ int sh[1024];
    int gid = blockIdx.x * 1024 + threadIdx.x;
    int v = (gid < n) ? g_rowptr[gid] : 0;
    sh[threadIdx.x] = v;
    __syncthreads();
    #pragma unroll
    for (int off = 1; off < 1024; off <<= 1) {
        int t = (threadIdx.x >= off) ? sh[threadIdx.x - off] : 0;
        __syncthreads();
        sh[threadIdx.x] += t;
        __syncthreads();
    }
    if (gid < n) g_rowptr[gid] = sh[threadIdx.x];
    if (threadIdx.x == 1023) g_bsum[blockIdx.x] = sh[1023];
}
__global__ void csr_scan2_kernel(int nb) {
    __shared__ int sh[1024];
    int v = (threadIdx.x < nb) ? g_bsum[threadIdx.x] : 0;
    sh[threadIdx.x] = v;
    __syncthreads();
    #pragma unroll
    for (int off = 1; off < 1024; off <<= 1) {
        int t = (threadIdx.x >= off) ? sh[threadIdx.x - off] : 0;
        __syncthreads();
        sh[threadIdx.x] += t;
        __syncthreads();
    }
    if (threadIdx.x < nb) g_bsum[threadIdx.x] = sh[threadIdx.x] - v;
}
__global__ void csr_scan3_kernel(int n) {
    int gid = blockIdx.x * 1024 + threadIdx.x;
    if (gid < n) g_rowptr[gid] += g_bsum[blockIdx.x];
}
__global__ void csr_fill_kernel() {
    int i = blockIdx.x * blockDim.x + threadIdx.x;
    if (i < N_NODES) g_fill[i] = g_rowptr[i];
}
__global__ void csr_place_kernel(const int* __restrict__ ei,
                                 const int* __restrict__ ea) {
    int e = blockIdx.x * blockDim.x + threadIdx.x;
    if (e >= N_EDGES) return;
    int d = ei[N_EDGES + e];
    int pos = atomicAdd(&g_fill[d], 1);
    int t = ea[2 * e] * 3 + ea[2 * e + 1];
    g_esrc[pos] = ((uint32_t)ei[e] << 4) | (uint32_t)t;
}

// ------- gather with optional fused BN+relu on loaded values -------
// dst[i] = f(src[i]) + tab0 + sum_in (f(src[s]) + tab[t]),  f = BN-affine+relu or identity
__global__ __launch_bounds__(256) void gather_kernel(
        const float* __restrict__ src, float* __restrict__ dst, int applyBN) {
    int node = blockIdx.x * 8 + (threadIdx.x >> 5);
    if (node >= N_NODES) return;
    int lane = threadIdx.x & 31;
    int beg = g_rowptr[node], end = g_rowptr[node + 1];
    const int c0 = lane, c1 = lane + 32, c2 = lane + 64;   // c2 valid iff lane < 11

    float4 z = make_float4(0, 0, 0, 0);
    float4 sc0 = z, sc1 = z, sc2 = z, of0 = z, of1 = z, of2 = z;
    if (applyBN) {
        const float4* scp = (const float4*)g_bnco;
        const float4* ofp = (const float4*)(g_bnco + EMB);
        sc0 = scp[c0]; of0 = ofp[c0];
        sc1 = scp[c1]; of1 = ofp[c1];
        if (lane < 11) { sc2 = scp[c2]; of2 = ofp[c2]; }
    }

    const float4* hd = (const float4*)(src + (size_t)node * EMB);
    const float4* t0 = (const float4*)g_tab;

    float4 v0 = hd[c0], v1 = hd[c1], v2 = (lane < 11) ? hd[c2] : z;
    if (applyBN) {
        v0 = bnrelu4(v0, sc0, of0);
        v1 = bnrelu4(v1, sc1, of1);
        if (lane < 11) v2 = bnrelu4(v2, sc2, of2);
    }
    float4 a0 = f4add(v0, t0[c0]);
    float4 a1 = f4add(v1, t0[c1]);
    float4 a2 = (lane < 11) ? f4add(v2, t0[c2]) : z;

    for (int e = beg; e < end; ++e) {
        uint32_t v = g_esrc[e];
        const float4* hs = (const float4*)(src + (size_t)(v >> 4) * EMB);
        const float4* tb = (const float4*)(g_tab + (v & 15u) * EMB);
        float4 w0 = hs[c0], w1 = hs[c1], w2 = (lane < 11) ? hs[c2] : z;
        if (applyBN) {
            w0 = bnrelu4(w0, sc0, of0);
            w1 = bnrelu4(w1, sc1, of1);
            if (lane < 11) w2 = bnrelu4(w2, sc2, of2);
        }
        a0 = f4add(a0, f4add(w0, tb[c0]));
        a1 = f4add(a1, f4add(w1, tb[c1]));
        if (lane < 11) a2 = f4add(a2, f4add(w2, tb[c2]));
    }
    float4* ag = (float4*)(dst + (size_t)node * EMB);
    ag[c0] = a0;
    ag[c1] = a1;
    if (lane < 11) ag[c2] = a2;
}

// ---------------- weight transpose + fp16 hi/lo split ----------------
__global__ void transpose_split_kernel(const float* __restrict__ W,
                                       int N, int K, int Npad, int Kpad) {
    __shared__ float tile[32][33];
    int tx = threadIdx.x, ty = threadIdx.y;
    int nb = blockIdx.x * 32, kb = blockIdx.y * 32;
    #pragma unroll
    for (int j = 0; j < 4; ++j) {
        int gk = kb + ty + j * 8, gn = nb + tx;
        tile[ty + j * 8][tx] = (gk < K && gn < N) ? W[(size_t)gk * N + gn] : 0.f;
    }
    __syncthreads();
    #pragma unroll
    for (int j = 0; j < 4; ++j) {
        int gn = nb + ty + j * 8, gk = kb + tx;
        if (gn < Npad && gk < Kpad) {
            float v = tile[tx][ty + j * 8];
            __half hi = __float2half_rn(v);
            __half lo = __float2half_rn(v - __half2float(hi));
            g_wth[(size_t)gn * Kpad + gk] = hi;
            g_wtl[(size_t)gn * Kpad + gk] = lo;
        }
    }
}

// ====== unified 3-term split-fp16 GEMM: 128x64 CTA tile, double-buffered ======
#define KT 32
#define WSTRIDE 20
#define AH_OFF  0
#define AL_OFF  (128 * WSTRIDE)
#define BH_OFF  (256 * WSTRIDE)
#define BL_OFF  (320 * WSTRIDE)
#define STAGEW  (384 * WSTRIDE)
#define GEMM_SMEM (2 * STAGEW * 4)     // 61440 B

__device__ __forceinline__ void mma16f(float* c, const uint32_t* a, const uint32_t* b) {
    asm volatile(
        "mma.sync.aligned.m16n8k16.row.col.f32.f16.f16.f32 "
        "{%0,%1,%2,%3},{%4,%5,%6,%7},{%8,%9},{%0,%1,%2,%3};\n"
        : "+f"(c[0]), "+f"(c[1]), "+f"(c[2]), "+f"(c[3])
        : "r"(a[0]), "r"(a[1]), "r"(a[2]), "r"(a[3]), "r"(b[0]), "r"(b[1]));
}
__device__ __forceinline__ void ldmx4(uint32_t* r, uint32_t addr) {
    asm volatile("ldmatrix.sync.aligned.m8n8.x4.shared.b16 {%0,%1,%2,%3}, [%4];"
        : "=r"(r[0]), "=r"(r[1]), "=r"(r[2]), "=r"(r[3]) : "r"(addr));
}

__device__ __forceinline__ void split4h(float4 f, uint2& hi, uint2& lo) {
    __half h0 = __float2half_rn(f.x), h1 = __float2half_rn(f.y),
           h2 = __float2half_rn(f.z), h3 = __float2half_rn(f.w);
    __half l0 = __float2half_rn(f.x - __half2float(h0)),
           l1 = __float2half_rn(f.y - __half2float(h1)),
           l2 = __float2half_rn(f.z - __half2float(h2)),
           l3 = __float2half_rn(f.w - __half2float(h3));
    __half2 ha = __halves2half2(h0, h1), hb = __halves2half2(h2, h3);
    __half2 la = __halves2half2(l0, l1), lb = __halves2half2(l2, l3);
    hi = make_uint2(*(uint32_t*)&ha, *(uint32_t*)&hb);
    lo = make_uint2(*(uint32_t*)&la, *(uint32_t*)&lb);
}

__global__ __launch_bounds__(256, 2) void gemm_n64_kernel(
        const float* __restrict__ A,
        const __half* __restrict__ Wh,
        const __half* __restrict__ Wl,
        const float* __restrict__ bias, float* __restrict__ C,
        int M, int N, int K, int Kpad, int doRelu, int doStats) {
    extern __shared__ __align__(16) uint32_t sm[];

    const int tid  = threadIdx.x;
    const int lane = tid & 31;
    const int warp = tid >> 5;
    const int g = lane >> 2;
    const int t = lane & 3;
    const int wm = (warp & 3) * 32;
    const int wn = (warp >> 2) * 32;
    const int row0 = blockIdx.y * 128;
    const int col0 = blockIdx.x * 64;

    const uint32_t sb0 = smem_u32(sm);

    const int l8  = lane & 7;
    const int sel = lane >> 3;
    const int a_row  = l8 + ((sel & 1) << 3);
    const int a_koff = ((sel >> 1) << 3) * 2;
    const int b_row  = l8 + ((sel >> 1) << 3);
    const int b_koff = ((sel & 1) << 3) * 2;

    float c[2][4][4] = {};
    float4 ra[4];
    uint4  rb[2];

    const int nk = (K + KT - 1) / KT;

    #pragma unroll
    for (int it = 0; it < 4; ++it) {
        int idx = tid + it * 256;
        int r = idx >> 3, kq = idx & 7;
        int gr = row0 + r, gk = kq * 4;
        ra[it] = (gr < M && gk < K) ? *(const float4*)(A + (size_t)gr * K + gk)
                                    : make_float4(0.f, 0.f, 0.f, 0.f);
    }
    #pragma unroll
    for (int it = 0; it < 2; ++it) {
        int idx = tid + it * 256;
        int term = idx >> 8, rem = idx & 255;
        int r = rem >> 2, q = rem & 3;
        rb[it] = *(const uint4*)((term ? Wl : Wh) + (size_t)(col0 + r) * Kpad + q * 8);
    }
    {
        uint32_t* S = sm;
        #pragma unroll
        for (int it = 0; it < 4; ++it) {
            int idx = tid + it * 256;
            int r = idx >> 3, kq = idx & 7;
            uint2 hi, lo;
            split4h(ra[it], hi, lo);
            *(uint2*)&S[AH_OFF + r * WSTRIDE + kq * 2] = hi;
            *(uint2*)&S[AL_OFF + r * WSTRIDE + kq * 2] = lo;
        }
        #pragma unroll
        for (int it = 0; it < 2; ++it) {
            int idx = tid + it * 256;
            int term = idx >> 8, rem = idx & 255;
            int r = rem >> 2, q = rem & 3;
            *(uint4*)&S[(term ? BL_OFF : BH_OFF) + r * WSTRIDE + q * 4] = rb[it];
        }
    }
    __syncthreads();

    for (int kt = 0; kt < nk; ++kt) {
        const uint32_t sb = sb0 + (kt & 1) * (STAGEW * 4);

        if (kt + 1 < nk) {
            int k0 = (kt + 1) * KT;
            #pragma unroll
            for (int it = 0; it < 4; ++it) {
                int idx = tid + it * 256;
                int r = idx >> 3, kq = idx & 7;
                int gr = row0 + r, gk = k0 + kq * 4;
                ra[it] = (gr < M && gk < K) ? *(const float4*)(A + (size_t)gr * K + gk)
                                            : make_float4(0.f, 0.f, 0.f, 0.f);
            }
            #pragma unroll
            for (int it = 0; it < 2; ++it) {
                int idx = tid + it * 256;
                int term = idx >> 8, rem = idx & 255;
                int r = rem >> 2, q = rem & 3;
                rb[it] = *(const uint4*)((term ? Wl : Wh) +
                         (size_t)(col0 + r) * Kpad + k0 + q * 8);
            }
        }

        const uint32_t sAh = sb + AH_OFF * 4;
        const uint32_t sAl = sb + AL_OFF * 4;
        const uint32_t sBh = sb + BH_OFF * 4;
        const uint32_t sBl = sb + BL_OFF * 4;
        #pragma unroll
        for (int ks = 0; ks < 2; ++ks) {
            const int ka = ks * 32 + a_koff;
            const int kb = ks * 32 + b_koff;
            uint32_t afh[2][4], afl[2][4], bfh[4][2], bfl[4][2];
            #pragma unroll
            for (int i = 0; i < 2; ++i) {
                uint32_t ro = (uint32_t)(wm + i * 16 + a_row) * 80 + ka;
                ldmx4(afh[i], sAh + ro);
                ldmx4(afl[i], sAl + ro);
            }
            #pragma unroll
            for (int j2 = 0; j2 < 2; ++j2) {
                uint32_t ro = (uint32_t)(wn + j2 * 16 + b_row) * 80 + kb;
                uint32_t r[4];
                ldmx4(r, sBh + ro);
                bfh[2 * j2][0] = r[0]; bfh[2 * j2][1] = r[1];
                bfh[2 * j2 + 1][0] = r[2]; bfh[2 * j2 + 1][1] = r[3];
                ldmx4(r, sBl + ro);
                bfl[2 * j2][0] = r[0]; bfl[2 * j2][1] = r[1];
                bfl[2 * j2 + 1][0] = r[2]; bfl[2 * j2 + 1][1] = r[3];
            }
            #pragma unroll
            for (int i = 0; i < 2; ++i)
                #pragma unroll
                for (int j = 0; j < 4; ++j) {
                    mma16f(c[i][j], afl[i], bfh[j]);
                    mma16f(c[i][j], afh[i], bfl[j]);
                    mma16f(c[i][j], afh[i], bfh[j]);
                }
        }

        if (kt + 1 < nk) {
            uint32_t* S = sm + ((kt + 1) & 1) * STAGEW;
            #pragma unroll
            for (int it = 0; it < 4; ++it) {
                int idx = tid + it * 256;
                int r = idx >> 3, kq = idx & 7;
                uint2 hi, lo;
                split4h(ra[it], hi, lo);
                *(uint2*)&S[AH_OFF + r * WSTRIDE + kq * 2] = hi;
                *(uint2*)&S[AL_OFF + r * WSTRIDE + kq * 2] = lo;
            }
            #pragma unroll
            for (int it = 0; it < 2; ++it) {
                int idx = tid + it * 256;
                int term = idx >> 8, rem = idx & 255;
                int r = rem >> 2, q = rem & 3;
                *(uint4*)&S[(term ? BL_OFF : BH_OFF) + r * WSTRIDE + q * 4] = rb[it];
            }
        }
        __syncthreads();
    }

    if (doStats) {
        #pragma unroll
        for (int j = 0; j < 4; ++j) {
            float s0 = 0.f, q0 = 0.f, s1 = 0.f, q1 = 0.f;
            #pragma unroll
            for (int i = 0; i < 2; ++i) {
                float v0 = c[i][j][0], v1 = c[i][j][1];
                float v2 = c[i][j][2], v3 = c[i][j][3];
                s0 += v0 + v2; q0 += v0 * v0 + v2 * v2;
                s1 += v1 + v3; q1 += v1 * v1 + v3 * v3;
            }
            #pragma unroll
            for (int m = 4; m < 32; m <<= 1) {
                s0 += __shfl_xor_sync(0xFFFFFFFFu, s0, m);
                q0 += __shfl_xor_sync(0xFFFFFFFFu, q0, m);
                s1 += __shfl_xor_sync(0xFFFFFFFFu, s1, m);
                q1 += __shfl_xor_sync(0xFFFFFFFFu, q1, m);
            }
            if (lane < 4) {
                int cc = col0 + wn + j * 8 + 2 * t;
                if (cc < EMB) {
                    atomicAdd(&g_stats[cc], s0);
                    atomicAdd(&g_stats[EMB + cc], q0);
                }
                if (cc + 1 < EMB) {
                    atomicAdd(&g_stats[cc + 1], s1);
                    atomicAdd(&g_stats[EMB + cc + 1], q1);
                }
            }
        }
        #pragma unroll
        for (int i = 0; i < 2; ++i) {
            int r = row0 + wm + i * 16 + g;
            #pragma unroll
            for (int j = 0; j < 4; ++j) {
                int cc = col0 + wn + j * 8 + 2 * t;
                if (cc >= N) continue;
                if (r < M)
                    *(float2*)&C[(size_t)r * N + cc] = make_float2(c[i][j][0], c[i][j][1]);
                int r2 = r + 8;
                if (r2 < M)
                    *(float2*)&C[(size_t)r2 * N + cc] = make_float2(c[i][j][2], c[i][j][3]);
            }
        }
    } else {
        #pragma unroll
        for (int i = 0; i < 2; ++i) {
            int r = row0 + wm + i * 16 + g;
            #pragma unroll
            for (int j = 0; j < 4; ++j) {
                int cc = col0 + wn + j * 8 + 2 * t;
                if (cc >= N) continue;
                float bx = bias[cc], by = bias[cc + 1];
                if (r < M) {
                    float2 v = make_float2(c[i][j][0] + bx, c[i][j][1] + by);
                    if (doRelu) { v.x = fmaxf(v.x, 0.f); v.y = fmaxf(v.y, 0.f); }
                    *(float2*)&C[(size_t)r * N + cc] = v;
                }
                int r2 = r + 8;
                if (r2 < M) {
                    float2 v = make_float2(c[i][j][2] + bx, c[i][j][3] + by);
                    if (doRelu) { v.x = fmaxf(v.x, 0.f); v.y = fmaxf(v.y, 0.f); }
                    *(float2*)&C[(size_t)r2 * N + cc] = v;
                }
            }
        }
    }
}

// -------- final-layer BN apply + pooled scatter (no relu) --------
__global__ void bn_pool_kernel(const float* __restrict__ X,
                               const float* __restrict__ gamma,
                               const float* __restrict__ beta,
                               const int* __restrict__ batch,
                               float* __restrict__ out, int l) {
    int idx = blockIdx.x * blockDim.x + threadIdx.x;
    if (idx >= N_NODES * EMB) return;
    int c = idx % EMB;
    float mu  = g_stats[c] * (1.f / N_NODES);
    float var = fmaxf(g_stats[EMB + c] * (1.f / N_NODES) - mu * mu, 0.f);
    float sc = rsqrtf(var + BN_EPS) * gamma[l * EMB + c];
    float v = (X[idx] - mu) * sc + beta[l * EMB + c];
    int i = idx / EMB;
    atomicAdd(&out[(size_t)batch[i] * EMB + c], v);
}

// ---------------- pooling ----------------
__global__ void pool_zero_kernel(float* __restrict__ out) {
    int idx = blockIdx.x * blockDim.x + threadIdx.x;
    if (idx < NUM_GRAPHS) g_counts[idx] = 0.f;
    if (idx < NUM_GRAPHS * EMB) out[idx] = 0.f;
}
__global__ void pool_count_kernel(const int* __restrict__ batch) {
    int i = blockIdx.x * blockDim.x + threadIdx.x;
    if (i >= N_NODES) return;
    atomicAdd(&g_counts[batch[i]], 1.f);
}
__global__ void pool_div_kernel(float* __restrict__ out) {
    int idx = blockIdx.x * blockDim.x + threadIdx.x;
    if (idx >= NUM_GRAPHS * EMB) return;
    out[idx] /= fmaxf(g_counts[idx / EMB], 1.f);
}

// ---------------- launch ----------------
extern "C" void kernel_launch(void* const* d_in, const int* in_sizes, int n_in,
                              void* d_out, int out_size) {
    const int*   x        = (const int*)d_in[0];
    const int*   edge_idx = (const int*)d_in[1];
    const int*   edge_att = (const int*)d_in[2];
    const int*   batch    = (const int*)d_in[3];
    const float* x_emb1   = (const float*)d_in[4];
    const float* x_emb2   = (const float*)d_in[5];
    const float* edge_e1  = (const float*)d_in[6];
    const float* edge_e2  = (const float*)d_in[7];
    const float* W1       = (const float*)d_in[8];
    const float* b1       = (const float*)d_in[9];
    const float* W2       = (const float*)d_in[10];
    const float* b2       = (const float*)d_in[11];
    const float* gamma    = (const float*)d_in[12];
    const float* beta     = (const float*)d_in[13];
    float* out = (float*)d_out;
    (void)b2;  // b2 cancels inside BatchNorm

    const int NE = N_NODES * EMB;
    const int TPB = 256;

    cudaFuncSetAttribute(gemm_n64_kernel,
                         cudaFuncAttributeMaxDynamicSharedMemorySize, GEMM_SMEM);

    init_h_kernel<<<(NE + TPB - 1) / TPB, TPB>>>(x, x_emb1, x_emb2);

    // ---- build CSR once (graph constant across layers) ----
    const int NS = N_NODES + 1;
    const int SCAN_BLOCKS = (NS + 1023) / 1024;
    csr_zero_kernel<<<(NS + TPB - 1) / TPB, TPB>>>();
    csr_count_kernel<<<(N_EDGES + TPB - 1) / TPB, TPB>>>(edge_idx);
    csr_scan1_kernel<<<SCAN_BLOCKS, 1024>>>(NS);
    csr_scan2_kernel<<<1, 1024>>>(SCAN_BLOCKS);
    csr_scan3_kernel<<<SCAN_BLOCKS, 1024>>>(NS);
    csr_fill_kernel<<<(N_NODES + TPB - 1) / TPB, TPB>>>();
    csr_place_kernel<<<(N_EDGES + TPB - 1) / TPB, TPB>>>(edge_idx, edge_att);

    float *p_h, *p_agg, *p_t;
    __half *p_wh, *p_wl;
    cudaGetSymbolAddress((void**)&p_h, g_h);
    cudaGetSymbolAddress((void**)&p_agg, g_agg);
    cudaGetSymbolAddress((void**)&p_t, g_t);
    cudaGetSymbolAddress((void**)&p_wh, g_wth);
    cudaGetSymbolAddress((void**)&p_wl, g_wtl);

    const int MT = (N_NODES + 127) / 128;
    dim3 tb(32, 8);
    dim3 tr1(640 / 32, 320 / 32);
    dim3 tr2(384 / 32, 640 / 32);
    dim3 gg1(10, MT);
    dim3 gg2(5, MT);

    for (int l = 0; l < NUM_LAYER; ++l) {
        // BN coefficients from previous layer's stats (before zeroing)
        if (l > 0) bnco_kernel<<<2, 256>>>(gamma, beta, l - 1);
        zero_stats_kernel<<<3, 256>>>();
        build_tab_kernel<<<(9 * EMB + TPB - 1) / TPB, TPB>>>(edge_e1, edge_e2, l);

        // gather: layer 0 reads g_h (init) -> g_agg; layers >=1 read g_agg (y) with
        // fused BN+relu -> g_h
        const float* gsrc = (l == 0) ? p_h : p_agg;
        float* gdst       = (l == 0) ? p_agg : p_h;
        gather_kernel<<<(N_NODES + 7) / 8, 256>>>(gsrc, gdst, l > 0);
        const float* A1 = gdst;

        // t = relu(agg @ W1[l] + b1[l])   [N, 600]
        transpose_split_kernel<<<tr1, tb>>>(W1 + (size_t)l * EMB * EMB2,
                                            EMB2, EMB, 640, 320);
        gemm_n64_kernel<<<gg1, 256, GEMM_SMEM>>>(A1, p_wh, p_wl,
                                                 b1 + l * EMB2, p_t,
                                                 N_NODES, EMB2, EMB, 320, 1, 0);
        // y = t @ W2[l]   [N, 300]  (bias cancels in BN; stats fused)
        transpose_split_kernel<<<tr2, tb>>>(W2 + (size_t)l * EMB2 * EMB,
                                            EMB, EMB2, 384, 640);
        gemm_n64_kernel<<<gg2, 256, GEMM_SMEM>>>(p_t, p_wh, p_wl,
                                                 b2, p_agg,
                                                 N_NODES, EMB, EMB2, 640, 0, 1);
    }

    // final layer: BN apply (no relu) + mean pool
    pool_zero_kernel<<<(NUM_GRAPHS * EMB + TPB - 1) / TPB, TPB>>>(out);
    pool_count_kernel<<<(N_NODES + TPB - 1) / TPB, TPB>>>(batch);
    bn_pool_kernel<<<(NE + TPB - 1) / TPB, TPB>>>(p_agg, gamma, beta, batch, out,
                                                  NUM_LAYER - 1);
    pool_div_kernel<<<(NUM_GRAPHS * EMB + TPB - 1) / TPB, TPB>>>(out);
}